// round 11
// baseline (speedup 1.0000x reference)
#include <cuda_runtime.h>
#include <cuda_fp16.h>
#include <math.h>
#include <stdint.h>

#define NN 50000
#define NE 1600000
#define CH 128
#define FE 50
#define TS 132
#define NTAB 16384
#define NCHUNK (NE / 32)

__device__ __half2 g_h2[(size_t)NN * 64];            // h in fp16, packed pairs
__device__ float g_agg[(size_t)NN * CH];
__device__ float g_table[(size_t)(NTAB + 1) * CH];
__device__ __half2 g_tab2[(size_t)NTAB * CH];
__device__ float4 g_Wp0[8192];   // W_lin  (fragment-packed tf32 hi/lo)
__device__ float4 g_Wp1[8192];   // Wm1
__device__ float4 g_Wp2[8192];   // Wm2

__device__ __forceinline__ float ssp(float x) {
    return fmaxf(x, 0.0f) + log1pf(__expf(-fabsf(x))) - 0.69314718055994530942f;
}
__device__ __forceinline__ void red_add_v4(float* addr, float4 v) {
    asm volatile("red.global.add.v4.f32 [%0], {%1,%2,%3,%4};"
                 :: "l"(addr), "f"(v.x), "f"(v.y), "f"(v.z), "f"(v.w) : "memory");
}
__device__ __forceinline__ void split_tf32(float x, uint32_t& hi, uint32_t& lo) {
    asm("cvt.rna.tf32.f32 %0, %1;" : "=r"(hi) : "f"(x));
    float r = x - __uint_as_float(hi);
    asm("cvt.rna.tf32.f32 %0, %1;" : "=r"(lo) : "f"(r));
}
#define MMA(c, a0, a1, a2, a3, b0, b1)                                        \
    asm volatile("mma.sync.aligned.m16n8k8.row.col.f32.tf32.tf32.f32 "        \
                 "{%0,%1,%2,%3}, {%4,%5,%6,%7}, {%8,%9}, {%0,%1,%2,%3};"      \
                 : "+f"((c)[0]), "+f"((c)[1]), "+f"((c)[2]), "+f"((c)[3])     \
                 : "r"(a0), "r"(a1), "r"(a2), "r"(a3), "r"(b0), "r"(b1));

#define FMA8(ar, av, w0, w1)                 \
    ar[0] = fmaf(av, w0.x, ar[0]);           \
    ar[1] = fmaf(av, w0.y, ar[1]);           \
    ar[2] = fmaf(av, w0.z, ar[2]);           \
    ar[3] = fmaf(av, w0.w, ar[3]);           \
    ar[4] = fmaf(av, w1.x, ar[4]);           \
    ar[5] = fmaf(av, w1.y, ar[5]);           \
    ar[6] = fmaf(av, w1.z, ar[6]);           \
    ar[7] = fmaf(av, w1.w, ar[7]);

// ---------------------------------------------------------------------------
__global__ void zero_agg_kernel() {
    size_t i = (size_t)blockIdx.x * blockDim.x + threadIdx.x;
    size_t stride = (size_t)gridDim.x * blockDim.x;
    float4* p = reinterpret_cast<float4*>(g_agg);
    const size_t n4 = (size_t)NN * CH / 4;
    float4 z = make_float4(0.f, 0.f, 0.f, 0.f);
    for (; i < n4; i += stride) p[i] = z;
}

__global__ void tab2_kernel() {
    int idx = blockIdx.x * blockDim.x + threadIdx.x;
    if (idx < NTAB * CH) {
        int i = idx >> 7, c = idx & 127;
        float a = g_table[(size_t)i * CH + c];
        float b = g_table[(size_t)(i + 1) * CH + c];
        g_tab2[(size_t)i * CH + c] = __floats2half2_rn(a, b);
    }
}

__global__ void prep_pack_kernel(const float* __restrict__ W_lin,
                                 const float* __restrict__ Wm1,
                                 const float* __restrict__ Wm2)
{
    int idx = blockIdx.x * blockDim.x + threadIdx.x;
    if (idx >= 3 * 8192) return;
    int m = idx / 8192, r = idx - m * 8192;
    int lane = r & 31, jk = r >> 5;
    int kq = jk & 15, j = jk >> 4;
    int g = lane >> 2, t = lane & 3;
    int n = j * 8 + g, k0 = kq * 8;
    float b0, b1;
    if (m == 0) {
        b0 = W_lin[n * CH + k0 + t];
        b1 = W_lin[n * CH + k0 + 4 + t];
    } else {
        const float* Wm = (m == 1) ? Wm1 : Wm2;
        b0 = Wm[(k0 + t) * CH + n];
        b1 = Wm[(k0 + 4 + t) * CH + n];
    }
    uint32_t h0, l0, h1, l1;
    split_tf32(b0, h0, l0);
    split_tf32(b1, h1, l1);
    float4 v = make_float4(__uint_as_float(h0), __uint_as_float(h1),
                           __uint_as_float(l0), __uint_as_float(l1));
    if (m == 0) g_Wp0[r] = v; else if (m == 1) g_Wp1[r] = v; else g_Wp2[r] = v;
}

// ---------------------------------------------------------------------------
// 3xTF32 warp-MMA GEMM, weights from fragment-packed global image (L1-hot).
// ---------------------------------------------------------------------------
__device__ __forceinline__ void gemm_pk(const float* __restrict__ As,
                                        const float4* __restrict__ P,
                                        float* acc, int m0, int lane)
{
    const int g = lane >> 2, t = lane & 3;
    const float* arow0 = As + (m0 + g) * TS + t;
    const float* arow1 = As + (m0 + g + 8) * TS + t;
    #pragma unroll 1
    for (int kq = 0; kq < 16; kq++) {
        const int k0 = kq * 8;
        uint32_t ah[4], al[4];
        split_tf32(arow0[k0],     ah[0], al[0]);
        split_tf32(arow1[k0],     ah[1], al[1]);
        split_tf32(arow0[k0 + 4], ah[2], al[2]);
        split_tf32(arow1[k0 + 4], ah[3], al[3]);
        #pragma unroll
        for (int j = 0; j < 16; j++) {
            float4 w = __ldg(P + ((j << 4) + kq) * 32 + lane);
            uint32_t bh0 = __float_as_uint(w.x), bh1 = __float_as_uint(w.y);
            uint32_t bl0 = __float_as_uint(w.z), bl1 = __float_as_uint(w.w);
            float* c = acc + j * 4;
            MMA(c, ah[0], ah[1], ah[2], ah[3], bh0, bh1);
            MMA(c, al[0], al[1], al[2], al[3], bh0, bh1);
            MMA(c, ah[0], ah[1], ah[2], ah[3], bl0, bl1);
        }
    }
}

// ---------------------------------------------------------------------------
// h = features @ W_lin^T, emitted as fp16 pairs into g_h2.
// ---------------------------------------------------------------------------
__global__ __launch_bounds__(256, 2)
void node_linear_kernel(const float* __restrict__ feat)
{
    extern __shared__ float sm[];
    float* As = sm;                       // [128][TS]
    const int tid = threadIdx.x;
    const int lane = tid & 31;
    const int m0 = (tid >> 5) * 16;
    const int n0 = blockIdx.x * 128;

    for (int i = tid; i < 128 * 32; i += 256) {
        int r = i >> 5, k4 = i & 31;
        int n = n0 + r;
        float4 v = make_float4(0.f, 0.f, 0.f, 0.f);
        if (n < NN) v = reinterpret_cast<const float4*>(feat)[(size_t)n * 32 + k4];
        *reinterpret_cast<float4*>(As + r * TS + k4 * 4) = v;
    }
    __syncthreads();

    float acc[64];
    #pragma unroll
    for (int i = 0; i < 64; i++) acc[i] = 0.f;
    gemm_pk(As, g_Wp0, acc, m0, lane);
    __syncthreads();

    const int g = lane >> 2, t = lane & 3;
    #pragma unroll
    for (int j = 0; j < 16; j++) {
        int col = j * 8 + 2 * t;
        *reinterpret_cast<float2*>(As + (m0 + g) * TS + col)     = make_float2(acc[j*4+0], acc[j*4+1]);
        *reinterpret_cast<float2*>(As + (m0 + g + 8) * TS + col) = make_float2(acc[j*4+2], acc[j*4+3]);
    }
    __syncthreads();

    for (int i = tid; i < 128 * 16; i += 256) {
        int r = i >> 4, q = i & 15;
        int n = n0 + r;
        if (n < NN) {
            const float* src = As + r * TS + q * 8;
            __half2 h0 = __floats2half2_rn(src[0], src[1]);
            __half2 h1 = __floats2half2_rn(src[2], src[3]);
            __half2 h2 = __floats2half2_rn(src[4], src[5]);
            __half2 h3 = __floats2half2_rn(src[6], src[7]);
            uint4 pk = make_uint4(*(uint32_t*)&h0, *(uint32_t*)&h1,
                                  *(uint32_t*)&h2, *(uint32_t*)&h3);
            reinterpret_cast<uint4*>(g_h2)[(size_t)n * 16 + q] = pk;
        }
    }
}

// ---------------------------------------------------------------------------
// out = ssp(agg @ Wm1 + bm1) @ Wm2 + bm2
// ---------------------------------------------------------------------------
__global__ __launch_bounds__(256, 2)
void out_mlp_kernel(const float* __restrict__ bm1, const float* __restrict__ bm2,
                    float* __restrict__ out)
{
    extern __shared__ float sm[];
    float* As = sm;                       // [128][TS]
    float* bs = sm + 128 * TS;            // [128]
    const int tid = threadIdx.x;
    const int lane = tid & 31;
    const int m0 = (tid >> 5) * 16;
    const int n0 = blockIdx.x * 128;
    const int g = lane >> 2, t = lane & 3;

    if (tid < CH) bs[tid] = bm1[tid];
    for (int i = tid; i < 128 * 32; i += 256) {
        int r = i >> 5, k4 = i & 31;
        int n = n0 + r;
        float4 v = make_float4(0.f, 0.f, 0.f, 0.f);
        if (n < NN) v = reinterpret_cast<const float4*>(g_agg)[(size_t)n * 32 + k4];
        *reinterpret_cast<float4*>(As + r * TS + k4 * 4) = v;
    }
    __syncthreads();

    float acc[64];
    #pragma unroll
    for (int i = 0; i < 64; i++) acc[i] = 0.f;
    gemm_pk(As, g_Wp1, acc, m0, lane);
    __syncthreads();

    #pragma unroll
    for (int j = 0; j < 16; j++) {
        int col = j * 8 + 2 * t;
        float b0 = bs[col], b1 = bs[col + 1];
        *reinterpret_cast<float2*>(As + (m0 + g) * TS + col) =
            make_float2(ssp(acc[j*4+0] + b0), ssp(acc[j*4+1] + b1));
        *reinterpret_cast<float2*>(As + (m0 + g + 8) * TS + col) =
            make_float2(ssp(acc[j*4+2] + b0), ssp(acc[j*4+3] + b1));
    }
    __syncthreads();
    if (tid < CH) bs[tid] = bm2[tid];
    __syncthreads();

    #pragma unroll
    for (int i = 0; i < 64; i++) acc[i] = 0.f;
    gemm_pk(As, g_Wp2, acc, m0, lane);
    __syncthreads();

    #pragma unroll
    for (int j = 0; j < 16; j++) {
        int col = j * 8 + 2 * t;
        float b0 = bs[col], b1 = bs[col + 1];
        *reinterpret_cast<float2*>(As + (m0 + g) * TS + col) =
            make_float2(acc[j*4+0] + b0, acc[j*4+1] + b1);
        *reinterpret_cast<float2*>(As + (m0 + g + 8) * TS + col) =
            make_float2(acc[j*4+2] + b0, acc[j*4+3] + b1);
    }
    __syncthreads();

    for (int i = tid; i < 128 * 32; i += 256) {
        int r = i >> 5, k4 = i & 31;
        int n = n0 + r;
        if (n < NN)
            reinterpret_cast<float4*>(out)[(size_t)n * 32 + k4] =
                *reinterpret_cast<const float4*>(As + r * TS + k4 * 4);
    }
}

// ---------------------------------------------------------------------------
// Build table: ef(r_i), r_i = i*5/NTAB
// ---------------------------------------------------------------------------
__global__ __launch_bounds__(256, 1)
void table_kernel(const float* __restrict__ Wf1, const float* __restrict__ bf1,
                  const float* __restrict__ Wf2, const float* __restrict__ bf2)
{
    extern __shared__ float sm[];
    float* Wf1s  = sm;
    float* Wf2s  = Wf1s + FE * CH;
    float* bf1s  = Wf2s + CH * CH;
    float* bf2s  = bf1s + CH;
    float* basis = bf2s + CH;
    float* t1    = basis + 128 * 53;

    const int tid = threadIdx.x;
    const int e0 = blockIdx.x * 128;
    const float H = 5.0f / (float)NTAB;

    for (int i = tid; i < FE * CH; i += 256) Wf1s[i] = Wf1[i];
    for (int i = tid; i < CH * CH; i += 256) Wf2s[i] = Wf2[i];
    if (tid < CH) { bf1s[tid] = bf1[tid]; bf2s[tid] = bf2[tid]; }

    const float delta = 5.0f / 49.0f;
    const float coef  = 2401.0f / 50.0f;
    for (int i = tid; i < 128 * FE; i += 256) {
        int e = i / FE, f = i - e * FE;
        float r = (float)(e0 + e) * H;
        float d = r - delta * (float)f;
        basis[e * 53 + f] = __expf(-coef * d * d);
    }
    __syncthreads();

    const int ei = tid >> 4;
    const int c0 = (tid & 15) * 8;

    float acc[8][8];
    #pragma unroll
    for (int r = 0; r < 8; r++)
        #pragma unroll
        for (int j = 0; j < 8; j++) acc[r][j] = bf1s[c0 + j];

    #pragma unroll 2
    for (int f = 0; f < FE; f++) {
        float a[8];
        #pragma unroll
        for (int r = 0; r < 8; r++) a[r] = basis[(ei * 8 + r) * 53 + f];
        float4 w0 = *reinterpret_cast<const float4*>(Wf1s + f * CH + c0);
        float4 w1 = *reinterpret_cast<const float4*>(Wf1s + f * CH + c0 + 4);
        #pragma unroll
        for (int r = 0; r < 8; r++) { FMA8(acc[r], a[r], w0, w1); }
    }
    #pragma unroll
    for (int r = 0; r < 8; r++)
        #pragma unroll
        for (int j = 0; j < 8; j++)
            t1[(ei * 8 + r) * 130 + c0 + j] = ssp(acc[r][j]);
    __syncthreads();

    #pragma unroll
    for (int r = 0; r < 8; r++)
        #pragma unroll
        for (int j = 0; j < 8; j++) acc[r][j] = bf2s[c0 + j];

    #pragma unroll 2
    for (int k = 0; k < CH; k++) {
        float a[8];
        #pragma unroll
        for (int r = 0; r < 8; r++) a[r] = t1[(ei * 8 + r) * 130 + k];
        float4 w0 = *reinterpret_cast<const float4*>(Wf2s + k * CH + c0);
        float4 w1 = *reinterpret_cast<const float4*>(Wf2s + k * CH + c0 + 4);
        #pragma unroll
        for (int r = 0; r < 8; r++) { FMA8(acc[r], a[r], w0, w1); }
    }

    #pragma unroll
    for (int r = 0; r < 8; r++) {
        int row = e0 + ei * 8 + r;
        if (row <= NTAB) {
            float* dst = g_table + (size_t)row * CH + c0;
            *reinterpret_cast<float4*>(dst)     = make_float4(acc[r][0], acc[r][1], acc[r][2], acc[r][3]);
            *reinterpret_cast<float4*>(dst + 4) = make_float4(acc[r][4], acc[r][5], acc[r][6], acc[r][7]);
        }
    }
}

// ---------------------------------------------------------------------------
// Edge apply: warp owns 32 consecutive edges; processes ADJACENT PAIRS with
// next-pair prefetch (4 load streams in flight). fp16 table + fp16 h.
// ---------------------------------------------------------------------------
#define LOAD_EDGE(kk, tw, hw, ff)                                              \
    {                                                                          \
        float d_ = __shfl_sync(FULL, dl, (kk));                                \
        int   s_ = __shfl_sync(FULL, sl, (kk));                                \
        float u_ = d_ * SCALE;                                                 \
        int   i_ = (int)u_;                                                    \
        i_ = i_ < 0 ? 0 : (i_ > NTAB - 1 ? NTAB - 1 : i_);                     \
        ff = u_ - (float)i_;                                                   \
        tw = __ldg(reinterpret_cast<const uint4*>(                             \
                 g_tab2 + (size_t)i_ * CH) + lane);                            \
        hw = __ldg(reinterpret_cast<const uint2*>(                             \
                 g_h2 + (size_t)s_ * 64) + lane);                              \
    }

#define EDGE_MSG(tw, hw, ff, m)                                                \
    {                                                                          \
        float2 p0 = __half22float2(*reinterpret_cast<__half2*>(&tw.x));        \
        float2 p1 = __half22float2(*reinterpret_cast<__half2*>(&tw.y));        \
        float2 p2 = __half22float2(*reinterpret_cast<__half2*>(&tw.z));        \
        float2 p3 = __half22float2(*reinterpret_cast<__half2*>(&tw.w));        \
        float2 h01 = __half22float2(*reinterpret_cast<__half2*>(&hw.x));       \
        float2 h23 = __half22float2(*reinterpret_cast<__half2*>(&hw.y));       \
        m.x = fmaf(ff, p0.y - p0.x, p0.x) * h01.x;                             \
        m.y = fmaf(ff, p1.y - p1.x, p1.x) * h01.y;                             \
        m.z = fmaf(ff, p2.y - p2.x, p2.x) * h23.x;                             \
        m.w = fmaf(ff, p3.y - p3.x, p3.x) * h23.y;                             \
    }

__global__ __launch_bounds__(256, 8)
void edge_apply_kernel(const float* __restrict__ dist,
                       const int* __restrict__ senders,
                       const int* __restrict__ receivers)
{
    const int lane = threadIdx.x & 31;
    const int warp = (blockIdx.x * blockDim.x + threadIdx.x) >> 5;
    const int nwarps = (gridDim.x * blockDim.x) >> 5;
    const float SCALE = (float)NTAB / 5.0f;
    const unsigned FULL = 0xFFFFFFFFu;

    for (int c = warp; c < NCHUNK; c += nwarps) {
        const int e0 = c << 5;
        float dl = __ldg(dist + e0 + lane);
        int   sl = __ldg(senders + e0 + lane);
        int   rl = __ldg(receivers + e0 + lane);

        uint4 twA, twB;
        uint2 hwA, hwB;
        float fA, fB;
        LOAD_EDGE(0, twA, hwA, fA);
        LOAD_EDGE(1, twB, hwB, fB);

        #pragma unroll 1
        for (int k = 0; k < 32; k += 2) {
            const int kn = (k + 2 < 32) ? k + 2 : 30;
            uint4 twAn, twBn;
            uint2 hwAn, hwBn;
            float fAn, fBn;
            LOAD_EDGE(kn,     twAn, hwAn, fAn);
            LOAD_EDGE(kn + 1, twBn, hwBn, fBn);

            int r0 = __shfl_sync(FULL, rl, k);
            int r1 = __shfl_sync(FULL, rl, k + 1);
            float4 m0, m1;
            EDGE_MSG(twA, hwA, fA, m0);
            EDGE_MSG(twB, hwB, fB, m1);
            red_add_v4(g_agg + (size_t)r0 * CH + lane * 4, m0);
            red_add_v4(g_agg + (size_t)r1 * CH + lane * 4, m1);

            twA = twAn; hwA = hwAn; fA = fAn;
            twB = twBn; hwB = hwBn; fB = fBn;
        }
    }
}

// ---------------------------------------------------------------------------
extern "C" void kernel_launch(void* const* d_in, const int* in_sizes, int n_in,
                              void* d_out, int out_size)
{
    const float* features = (const float*)d_in[0];
    const float* dist     = (const float*)d_in[1];
    const float* W_lin    = (const float*)d_in[2];
    const float* Wf1      = (const float*)d_in[3];
    const float* bf1      = (const float*)d_in[4];
    const float* Wf2      = (const float*)d_in[5];
    const float* bf2      = (const float*)d_in[6];
    const float* Wm1      = (const float*)d_in[7];
    const float* bm1      = (const float*)d_in[8];
    const float* Wm2      = (const float*)d_in[9];
    const float* bm2      = (const float*)d_in[10];
    const int*   senders   = (const int*)d_in[11];
    const int*   receivers = (const int*)d_in[12];
    float* out = (float*)d_out;

    const int smemA = 128 * TS * 4;
    const int smemT = (FE * CH + CH * CH + 2 * CH + 128 * 53 + 128 * 130) * 4;
    const int smemC = (128 * TS + CH) * 4;

    cudaFuncSetAttribute(node_linear_kernel, cudaFuncAttributeMaxDynamicSharedMemorySize, smemA);
    cudaFuncSetAttribute(table_kernel,       cudaFuncAttributeMaxDynamicSharedMemorySize, smemT);
    cudaFuncSetAttribute(out_mlp_kernel,     cudaFuncAttributeMaxDynamicSharedMemorySize, smemC);

    zero_agg_kernel<<<1024, 256>>>();
    table_kernel<<<(NTAB + 1 + 127) / 128, 256, smemT>>>(Wf1, bf1, Wf2, bf2);
    tab2_kernel<<<(NTAB * CH + 255) / 256, 256>>>();
    prep_pack_kernel<<<96, 256>>>(W_lin, Wm1, Wm2);
    node_linear_kernel<<<(NN + 127) / 128, 256, smemA>>>(features);
    edge_apply_kernel<<<2048, 256>>>(dist, senders, receivers);
    out_mlp_kernel<<<(NN + 127) / 128, 256, smemC>>>(bm1, bm2, out);
}

// round 12
// speedup vs baseline: 1.4589x; 1.4589x over previous
#include <cuda_runtime.h>
#include <cuda_fp16.h>
#include <math.h>
#include <stdint.h>

#define NN 50000
#define NE 1600000
#define CH 128
#define FE 50
#define TS 132
#define NTAB 16384
#define NCHUNK (NE / 32)

__device__ __half2 g_h2[(size_t)NN * 64];            // h in fp16, packed pairs
__device__ float g_agg[(size_t)NN * CH];
__device__ float g_table[(size_t)(NTAB + 1) * CH];
__device__ __half2 g_tab2[(size_t)NTAB * CH];
// fp16-split fragment-packed weights: [j(16)][kq(8)][lane(32)] uint4 = (b0hi,b1hi,b0lo,b1lo)
__device__ uint4 g_Hp0[4096];    // W_lin
__device__ uint4 g_Hp1[4096];    // Wm1
__device__ uint4 g_Hp2[4096];    // Wm2

__device__ __forceinline__ float ssp(float x) {
    return fmaxf(x, 0.0f) + log1pf(__expf(-fabsf(x))) - 0.69314718055994530942f;
}
__device__ __forceinline__ void red_add_v4(float* addr, float4 v) {
    asm volatile("red.global.add.v4.f32 [%0], {%1,%2,%3,%4};"
                 :: "l"(addr), "f"(v.x), "f"(v.y), "f"(v.z), "f"(v.w) : "memory");
}
// split a float2 into fp16 hi/lo half2 pairs
__device__ __forceinline__ void split_h2(float x, float y, uint32_t& hi, uint32_t& lo) {
    __half2 h = __floats2half2_rn(x, y);
    float2 hb = __half22float2(h);
    __half2 l = __floats2half2_rn(x - hb.x, y - hb.y);
    hi = *reinterpret_cast<uint32_t*>(&h);
    lo = *reinterpret_cast<uint32_t*>(&l);
}
#define MMH(c, a, b0, b1)                                                     \
    asm volatile("mma.sync.aligned.m16n8k16.row.col.f32.f16.f16.f32 "         \
                 "{%0,%1,%2,%3}, {%4,%5,%6,%7}, {%8,%9}, {%0,%1,%2,%3};"      \
                 : "+f"((c)[0]), "+f"((c)[1]), "+f"((c)[2]), "+f"((c)[3])     \
                 : "r"((a)[0]), "r"((a)[1]), "r"((a)[2]), "r"((a)[3]),        \
                   "r"(b0), "r"(b1));

#define FMA8(ar, av, w0, w1)                 \
    ar[0] = fmaf(av, w0.x, ar[0]);           \
    ar[1] = fmaf(av, w0.y, ar[1]);           \
    ar[2] = fmaf(av, w0.z, ar[2]);           \
    ar[3] = fmaf(av, w0.w, ar[3]);           \
    ar[4] = fmaf(av, w1.x, ar[4]);           \
    ar[5] = fmaf(av, w1.y, ar[5]);           \
    ar[6] = fmaf(av, w1.z, ar[6]);           \
    ar[7] = fmaf(av, w1.w, ar[7]);

// ---------------------------------------------------------------------------
__global__ void zero_agg_kernel() {
    size_t i = (size_t)blockIdx.x * blockDim.x + threadIdx.x;
    size_t stride = (size_t)gridDim.x * blockDim.x;
    float4* p = reinterpret_cast<float4*>(g_agg);
    const size_t n4 = (size_t)NN * CH / 4;
    float4 z = make_float4(0.f, 0.f, 0.f, 0.f);
    for (; i < n4; i += stride) p[i] = z;
}

__global__ void tab2_kernel() {
    int idx = blockIdx.x * blockDim.x + threadIdx.x;
    if (idx < NTAB * CH) {
        int i = idx >> 7, c = idx & 127;
        float a = g_table[(size_t)i * CH + c];
        float b = g_table[(size_t)(i + 1) * CH + c];
        g_tab2[(size_t)i * CH + c] = __floats2half2_rn(a, b);
    }
}

// Pack weights into m16n8k16 fp16-split fragment order.
__global__ void prep_pack_kernel(const float* __restrict__ W_lin,
                                 const float* __restrict__ Wm1,
                                 const float* __restrict__ Wm2)
{
    int idx = blockIdx.x * blockDim.x + threadIdx.x;
    if (idx >= 3 * 4096) return;
    int m = idx / 4096, r = idx - m * 4096;
    int lane = r & 31, jk = r >> 5;
    int kq = jk & 7, j = jk >> 3;
    int g = lane >> 2, t = lane & 3;
    int n = j * 8 + g, k0 = kq * 16;

    float v0, v1, v2, v3;
    if (m == 0) {                        // B[n][k] = W_lin[n][k]
        v0 = W_lin[n * CH + k0 + 2 * t];
        v1 = W_lin[n * CH + k0 + 2 * t + 1];
        v2 = W_lin[n * CH + k0 + 2 * t + 8];
        v3 = W_lin[n * CH + k0 + 2 * t + 9];
    } else {                             // B[n][k] = Wm[k][n]
        const float* Wm = (m == 1) ? Wm1 : Wm2;
        v0 = Wm[(k0 + 2 * t) * CH + n];
        v1 = Wm[(k0 + 2 * t + 1) * CH + n];
        v2 = Wm[(k0 + 2 * t + 8) * CH + n];
        v3 = Wm[(k0 + 2 * t + 9) * CH + n];
    }
    uint32_t b0h, b0l, b1h, b1l;
    split_h2(v0, v1, b0h, b0l);
    split_h2(v2, v3, b1h, b1l);
    uint4 v = make_uint4(b0h, b1h, b0l, b1l);
    if (m == 0) g_Hp0[r] = v; else if (m == 1) g_Hp1[r] = v; else g_Hp2[r] = v;
}

// ---------------------------------------------------------------------------
// fp16-split warp-MMA GEMM (m16n8k16): 3 HMMA per (j, K=16).
// As fp32 [m][k] in smem; P packed weights in global (L1-hot).
// ---------------------------------------------------------------------------
__device__ __forceinline__ void gemm_h2(const float* __restrict__ As,
                                        const uint4* __restrict__ P,
                                        float* acc, int m0, int lane)
{
    const int g = lane >> 2, t = lane & 3;
    const float* r0 = As + (m0 + g) * TS + 2 * t;
    const float* r1 = As + (m0 + g + 8) * TS + 2 * t;
    #pragma unroll 1
    for (int kq = 0; kq < 8; kq++) {
        const int k0 = kq * 16;
        float2 x0 = *reinterpret_cast<const float2*>(r0 + k0);
        float2 x1 = *reinterpret_cast<const float2*>(r1 + k0);
        float2 x2 = *reinterpret_cast<const float2*>(r0 + k0 + 8);
        float2 x3 = *reinterpret_cast<const float2*>(r1 + k0 + 8);
        uint32_t ah[4], al[4];
        split_h2(x0.x, x0.y, ah[0], al[0]);
        split_h2(x1.x, x1.y, ah[1], al[1]);
        split_h2(x2.x, x2.y, ah[2], al[2]);
        split_h2(x3.x, x3.y, ah[3], al[3]);
        #pragma unroll
        for (int j = 0; j < 16; j++) {
            uint4 w = __ldg(P + ((j << 3) + kq) * 32 + lane);
            float* c = acc + j * 4;
            MMH(c, ah, w.x, w.y);        // ahi * bhi
            MMH(c, al, w.x, w.y);        // alo * bhi
            MMH(c, ah, w.z, w.w);        // ahi * blo
        }
    }
}

// ---------------------------------------------------------------------------
// h = features @ W_lin^T, emitted as fp16 pairs into g_h2.
// ---------------------------------------------------------------------------
__global__ __launch_bounds__(256, 2)
void node_linear_kernel(const float* __restrict__ feat)
{
    extern __shared__ float sm[];
    float* As = sm;                       // [128][TS]
    const int tid = threadIdx.x;
    const int lane = tid & 31;
    const int m0 = (tid >> 5) * 16;
    const int n0 = blockIdx.x * 128;

    for (int i = tid; i < 128 * 32; i += 256) {
        int r = i >> 5, k4 = i & 31;
        int n = n0 + r;
        float4 v = make_float4(0.f, 0.f, 0.f, 0.f);
        if (n < NN) v = reinterpret_cast<const float4*>(feat)[(size_t)n * 32 + k4];
        *reinterpret_cast<float4*>(As + r * TS + k4 * 4) = v;
    }
    __syncthreads();

    float acc[64];
    #pragma unroll
    for (int i = 0; i < 64; i++) acc[i] = 0.f;
    gemm_h2(As, g_Hp0, acc, m0, lane);
    __syncthreads();

    const int g = lane >> 2, t = lane & 3;
    #pragma unroll
    for (int j = 0; j < 16; j++) {
        int col = j * 8 + 2 * t;
        *reinterpret_cast<float2*>(As + (m0 + g) * TS + col)     = make_float2(acc[j*4+0], acc[j*4+1]);
        *reinterpret_cast<float2*>(As + (m0 + g + 8) * TS + col) = make_float2(acc[j*4+2], acc[j*4+3]);
    }
    __syncthreads();

    for (int i = tid; i < 128 * 16; i += 256) {
        int r = i >> 4, q = i & 15;
        int n = n0 + r;
        if (n < NN) {
            const float* src = As + r * TS + q * 8;
            __half2 h0 = __floats2half2_rn(src[0], src[1]);
            __half2 h1 = __floats2half2_rn(src[2], src[3]);
            __half2 h2 = __floats2half2_rn(src[4], src[5]);
            __half2 h3 = __floats2half2_rn(src[6], src[7]);
            uint4 pk = make_uint4(*(uint32_t*)&h0, *(uint32_t*)&h1,
                                  *(uint32_t*)&h2, *(uint32_t*)&h3);
            reinterpret_cast<uint4*>(g_h2)[(size_t)n * 16 + q] = pk;
        }
    }
}

// ---------------------------------------------------------------------------
// out = ssp(agg @ Wm1 + bm1) @ Wm2 + bm2
// ---------------------------------------------------------------------------
__global__ __launch_bounds__(256, 2)
void out_mlp_kernel(const float* __restrict__ bm1, const float* __restrict__ bm2,
                    float* __restrict__ out)
{
    extern __shared__ float sm[];
    float* As = sm;                       // [128][TS]
    float* bs = sm + 128 * TS;            // [128]
    const int tid = threadIdx.x;
    const int lane = tid & 31;
    const int m0 = (tid >> 5) * 16;
    const int n0 = blockIdx.x * 128;
    const int g = lane >> 2, t = lane & 3;

    if (tid < CH) bs[tid] = bm1[tid];
    for (int i = tid; i < 128 * 32; i += 256) {
        int r = i >> 5, k4 = i & 31;
        int n = n0 + r;
        float4 v = make_float4(0.f, 0.f, 0.f, 0.f);
        if (n < NN) v = reinterpret_cast<const float4*>(g_agg)[(size_t)n * 32 + k4];
        *reinterpret_cast<float4*>(As + r * TS + k4 * 4) = v;
    }
    __syncthreads();

    float acc[64];
    #pragma unroll
    for (int i = 0; i < 64; i++) acc[i] = 0.f;
    gemm_h2(As, g_Hp1, acc, m0, lane);
    __syncthreads();

    #pragma unroll
    for (int j = 0; j < 16; j++) {
        int col = j * 8 + 2 * t;
        float b0 = bs[col], b1 = bs[col + 1];
        *reinterpret_cast<float2*>(As + (m0 + g) * TS + col) =
            make_float2(ssp(acc[j*4+0] + b0), ssp(acc[j*4+1] + b1));
        *reinterpret_cast<float2*>(As + (m0 + g + 8) * TS + col) =
            make_float2(ssp(acc[j*4+2] + b0), ssp(acc[j*4+3] + b1));
    }
    __syncthreads();
    if (tid < CH) bs[tid] = bm2[tid];
    __syncthreads();

    #pragma unroll
    for (int i = 0; i < 64; i++) acc[i] = 0.f;
    gemm_h2(As, g_Hp2, acc, m0, lane);
    __syncthreads();

    #pragma unroll
    for (int j = 0; j < 16; j++) {
        int col = j * 8 + 2 * t;
        float b0 = bs[col], b1 = bs[col + 1];
        *reinterpret_cast<float2*>(As + (m0 + g) * TS + col) =
            make_float2(acc[j*4+0] + b0, acc[j*4+1] + b1);
        *reinterpret_cast<float2*>(As + (m0 + g + 8) * TS + col) =
            make_float2(acc[j*4+2] + b0, acc[j*4+3] + b1);
    }
    __syncthreads();

    for (int i = tid; i < 128 * 32; i += 256) {
        int r = i >> 5, k4 = i & 31;
        int n = n0 + r;
        if (n < NN)
            reinterpret_cast<float4*>(out)[(size_t)n * 32 + k4] =
                *reinterpret_cast<const float4*>(As + r * TS + k4 * 4);
    }
}

// ---------------------------------------------------------------------------
// Build table: ef(r_i), r_i = i*5/NTAB  (proven FFMA tile kernel)
// ---------------------------------------------------------------------------
__global__ __launch_bounds__(256, 1)
void table_kernel(const float* __restrict__ Wf1, const float* __restrict__ bf1,
                  const float* __restrict__ Wf2, const float* __restrict__ bf2)
{
    extern __shared__ float sm[];
    float* Wf1s  = sm;
    float* Wf2s  = Wf1s + FE * CH;
    float* bf1s  = Wf2s + CH * CH;
    float* bf2s  = bf1s + CH;
    float* basis = bf2s + CH;
    float* t1    = basis + 128 * 53;

    const int tid = threadIdx.x;
    const int e0 = blockIdx.x * 128;
    const float H = 5.0f / (float)NTAB;

    for (int i = tid; i < FE * CH; i += 256) Wf1s[i] = Wf1[i];
    for (int i = tid; i < CH * CH; i += 256) Wf2s[i] = Wf2[i];
    if (tid < CH) { bf1s[tid] = bf1[tid]; bf2s[tid] = bf2[tid]; }

    const float delta = 5.0f / 49.0f;
    const float coef  = 2401.0f / 50.0f;
    for (int i = tid; i < 128 * FE; i += 256) {
        int e = i / FE, f = i - e * FE;
        float r = (float)(e0 + e) * H;
        float d = r - delta * (float)f;
        basis[e * 53 + f] = __expf(-coef * d * d);
    }
    __syncthreads();

    const int ei = tid >> 4;
    const int c0 = (tid & 15) * 8;

    float acc[8][8];
    #pragma unroll
    for (int r = 0; r < 8; r++)
        #pragma unroll
        for (int j = 0; j < 8; j++) acc[r][j] = bf1s[c0 + j];

    #pragma unroll 2
    for (int f = 0; f < FE; f++) {
        float a[8];
        #pragma unroll
        for (int r = 0; r < 8; r++) a[r] = basis[(ei * 8 + r) * 53 + f];
        float4 w0 = *reinterpret_cast<const float4*>(Wf1s + f * CH + c0);
        float4 w1 = *reinterpret_cast<const float4*>(Wf1s + f * CH + c0 + 4);
        #pragma unroll
        for (int r = 0; r < 8; r++) { FMA8(acc[r], a[r], w0, w1); }
    }
    #pragma unroll
    for (int r = 0; r < 8; r++)
        #pragma unroll
        for (int j = 0; j < 8; j++)
            t1[(ei * 8 + r) * 130 + c0 + j] = ssp(acc[r][j]);
    __syncthreads();

    #pragma unroll
    for (int r = 0; r < 8; r++)
        #pragma unroll
        for (int j = 0; j < 8; j++) acc[r][j] = bf2s[c0 + j];

    #pragma unroll 2
    for (int k = 0; k < CH; k++) {
        float a[8];
        #pragma unroll
        for (int r = 0; r < 8; r++) a[r] = t1[(ei * 8 + r) * 130 + k];
        float4 w0 = *reinterpret_cast<const float4*>(Wf2s + k * CH + c0);
        float4 w1 = *reinterpret_cast<const float4*>(Wf2s + k * CH + c0 + 4);
        #pragma unroll
        for (int r = 0; r < 8; r++) { FMA8(acc[r], a[r], w0, w1); }
    }

    #pragma unroll
    for (int r = 0; r < 8; r++) {
        int row = e0 + ei * 8 + r;
        if (row <= NTAB) {
            float* dst = g_table + (size_t)row * CH + c0;
            *reinterpret_cast<float4*>(dst)     = make_float4(acc[r][0], acc[r][1], acc[r][2], acc[r][3]);
            *reinterpret_cast<float4*>(dst + 4) = make_float4(acc[r][4], acc[r][5], acc[r][6], acc[r][7]);
        }
    }
}

// ---------------------------------------------------------------------------
// Edge apply (EXACT R9 form — frozen): warp owns 32 consecutive edges,
// depth-1 prefetch; fp16 endpoint table + fp16 h; red.global scatter.
// ---------------------------------------------------------------------------
__global__ __launch_bounds__(256, 8)
void edge_apply_kernel(const float* __restrict__ dist,
                       const int* __restrict__ senders,
                       const int* __restrict__ receivers)
{
    const int lane = threadIdx.x & 31;
    const int warp = (blockIdx.x * blockDim.x + threadIdx.x) >> 5;
    const int nwarps = (gridDim.x * blockDim.x) >> 5;
    const float SCALE = (float)NTAB / 5.0f;
    const unsigned FULL = 0xFFFFFFFFu;

    for (int c = warp; c < NCHUNK; c += nwarps) {
        const int e0 = c << 5;
        float dl = __ldg(dist + e0 + lane);
        int   sl = __ldg(senders + e0 + lane);
        int   rl = __ldg(receivers + e0 + lane);

        float d0 = __shfl_sync(FULL, dl, 0);
        int   s0 = __shfl_sync(FULL, sl, 0);
        float u = d0 * SCALE;
        int   i = (int)u;  i = i < 0 ? 0 : (i > NTAB - 1 ? NTAB - 1 : i);
        float fcur = u - (float)i;
        uint4 tw = __ldg(reinterpret_cast<const uint4*>(
            g_tab2 + (size_t)i * CH) + lane);
        uint2 hw = __ldg(reinterpret_cast<const uint2*>(g_h2 + (size_t)s0 * 64) + lane);

        #pragma unroll 1
        for (int k = 0; k < 32; k++) {
            const int kn = (k + 1 < 32) ? k + 1 : 31;
            float dn = __shfl_sync(FULL, dl, kn);
            int   sn = __shfl_sync(FULL, sl, kn);
            float un = dn * SCALE;
            int   in = (int)un;  in = in < 0 ? 0 : (in > NTAB - 1 ? NTAB - 1 : in);
            float fn = un - (float)in;
            uint4 twn = __ldg(reinterpret_cast<const uint4*>(
                g_tab2 + (size_t)in * CH) + lane);
            uint2 hwn = __ldg(reinterpret_cast<const uint2*>(g_h2 + (size_t)sn * 64) + lane);

            int rk = __shfl_sync(FULL, rl, k);
            float2 p0 = __half22float2(*reinterpret_cast<__half2*>(&tw.x));
            float2 p1 = __half22float2(*reinterpret_cast<__half2*>(&tw.y));
            float2 p2 = __half22float2(*reinterpret_cast<__half2*>(&tw.z));
            float2 p3 = __half22float2(*reinterpret_cast<__half2*>(&tw.w));
            float2 h01 = __half22float2(*reinterpret_cast<__half2*>(&hw.x));
            float2 h23 = __half22float2(*reinterpret_cast<__half2*>(&hw.y));
            float4 m;
            m.x = fmaf(fcur, p0.y - p0.x, p0.x) * h01.x;
            m.y = fmaf(fcur, p1.y - p1.x, p1.x) * h01.y;
            m.z = fmaf(fcur, p2.y - p2.x, p2.x) * h23.x;
            m.w = fmaf(fcur, p3.y - p3.x, p3.x) * h23.y;
            red_add_v4(g_agg + (size_t)rk * CH + lane * 4, m);

            tw = twn; hw = hwn; fcur = fn;
        }
    }
}

// ---------------------------------------------------------------------------
extern "C" void kernel_launch(void* const* d_in, const int* in_sizes, int n_in,
                              void* d_out, int out_size)
{
    const float* features = (const float*)d_in[0];
    const float* dist     = (const float*)d_in[1];
    const float* W_lin    = (const float*)d_in[2];
    const float* Wf1      = (const float*)d_in[3];
    const float* bf1      = (const float*)d_in[4];
    const float* Wf2      = (const float*)d_in[5];
    const float* bf2      = (const float*)d_in[6];
    const float* Wm1      = (const float*)d_in[7];
    const float* bm1      = (const float*)d_in[8];
    const float* Wm2      = (const float*)d_in[9];
    const float* bm2      = (const float*)d_in[10];
    const int*   senders   = (const int*)d_in[11];
    const int*   receivers = (const int*)d_in[12];
    float* out = (float*)d_out;

    const int smemA = 128 * TS * 4;
    const int smemT = (FE * CH + CH * CH + 2 * CH + 128 * 53 + 128 * 130) * 4;
    const int smemC = (128 * TS + CH) * 4;

    cudaFuncSetAttribute(node_linear_kernel, cudaFuncAttributeMaxDynamicSharedMemorySize, smemA);
    cudaFuncSetAttribute(table_kernel,       cudaFuncAttributeMaxDynamicSharedMemorySize, smemT);
    cudaFuncSetAttribute(out_mlp_kernel,     cudaFuncAttributeMaxDynamicSharedMemorySize, smemC);

    zero_agg_kernel<<<1024, 256>>>();
    table_kernel<<<(NTAB + 1 + 127) / 128, 256, smemT>>>(Wf1, bf1, Wf2, bf2);
    tab2_kernel<<<(NTAB * CH + 255) / 256, 256>>>();
    prep_pack_kernel<<<48, 256>>>(W_lin, Wm1, Wm2);
    node_linear_kernel<<<(NN + 127) / 128, 256, smemA>>>(features);
    edge_apply_kernel<<<2048, 256>>>(dist, senders, receivers);
    out_mlp_kernel<<<(NN + 127) / 128, 256, smemC>>>(bm1, bm2, out);
}

// round 13
// speedup vs baseline: 1.5613x; 1.0702x over previous
#include <cuda_runtime.h>
#include <cuda_fp16.h>
#include <math.h>
#include <stdint.h>

#define NN 50000
#define NE 1600000
#define CH 128
#define FE 50
#define TS 132
#define NTAB 16384
#define NCHUNK (NE / 32)

__device__ __half2 g_h2[(size_t)NN * 64];            // h in fp16, packed pairs
__device__ float g_agg[(size_t)NN * CH];
__device__ float g_table[(size_t)(NTAB + 1) * CH];
__device__ __half2 g_tab2[(size_t)NTAB * CH];
// fp16-split fragment-packed weights: [j(16)][kq(8)][lane(32)] uint4 = (b0hi,b1hi,b0lo,b1lo)
__device__ uint4 g_Hp0[4096];    // W_lin
__device__ uint4 g_Hp1[4096];    // Wm1
__device__ uint4 g_Hp2[4096];    // Wm2

__device__ __forceinline__ float ssp(float x) {
    return fmaxf(x, 0.0f) + log1pf(__expf(-fabsf(x))) - 0.69314718055994530942f;
}
__device__ __forceinline__ void red_add_v4(float* addr, float4 v) {
    asm volatile("red.global.add.v4.f32 [%0], {%1,%2,%3,%4};"
                 :: "l"(addr), "f"(v.x), "f"(v.y), "f"(v.z), "f"(v.w) : "memory");
}
__device__ __forceinline__ void split_h2(float x, float y, uint32_t& hi, uint32_t& lo) {
    __half2 h = __floats2half2_rn(x, y);
    float2 hb = __half22float2(h);
    __half2 l = __floats2half2_rn(x - hb.x, y - hb.y);
    hi = *reinterpret_cast<uint32_t*>(&h);
    lo = *reinterpret_cast<uint32_t*>(&l);
}
#define MMH(c, a, b0, b1)                                                     \
    asm volatile("mma.sync.aligned.m16n8k16.row.col.f32.f16.f16.f32 "         \
                 "{%0,%1,%2,%3}, {%4,%5,%6,%7}, {%8,%9}, {%0,%1,%2,%3};"      \
                 : "+f"((c)[0]), "+f"((c)[1]), "+f"((c)[2]), "+f"((c)[3])     \
                 : "r"((a)[0]), "r"((a)[1]), "r"((a)[2]), "r"((a)[3]),        \
                   "r"(b0), "r"(b1));

#define FMA8(ar, av, w0, w1)                 \
    ar[0] = fmaf(av, w0.x, ar[0]);           \
    ar[1] = fmaf(av, w0.y, ar[1]);           \
    ar[2] = fmaf(av, w0.z, ar[2]);           \
    ar[3] = fmaf(av, w0.w, ar[3]);           \
    ar[4] = fmaf(av, w1.x, ar[4]);           \
    ar[5] = fmaf(av, w1.y, ar[5]);           \
    ar[6] = fmaf(av, w1.z, ar[6]);           \
    ar[7] = fmaf(av, w1.w, ar[7]);

// ---------------------------------------------------------------------------
__global__ void zero_agg_kernel() {
    size_t i = (size_t)blockIdx.x * blockDim.x + threadIdx.x;
    size_t stride = (size_t)gridDim.x * blockDim.x;
    float4* p = reinterpret_cast<float4*>(g_agg);
    const size_t n4 = (size_t)NN * CH / 4;
    float4 z = make_float4(0.f, 0.f, 0.f, 0.f);
    for (; i < n4; i += stride) p[i] = z;
}

__global__ void tab2_kernel() {
    int idx = blockIdx.x * blockDim.x + threadIdx.x;
    if (idx < NTAB * CH) {
        int i = idx >> 7, c = idx & 127;
        float a = g_table[(size_t)i * CH + c];
        float b = g_table[(size_t)(i + 1) * CH + c];
        g_tab2[(size_t)i * CH + c] = __floats2half2_rn(a, b);
    }
}

// Pack weights into m16n8k16 fp16-split fragment order.
__global__ void prep_pack_kernel(const float* __restrict__ W_lin,
                                 const float* __restrict__ Wm1,
                                 const float* __restrict__ Wm2)
{
    int idx = blockIdx.x * blockDim.x + threadIdx.x;
    if (idx >= 3 * 4096) return;
    int m = idx / 4096, r = idx - m * 4096;
    int lane = r & 31, jk = r >> 5;
    int kq = jk & 7, j = jk >> 3;
    int g = lane >> 2, t = lane & 3;
    int n = j * 8 + g, k0 = kq * 16;

    float v0, v1, v2, v3;
    if (m == 0) {                        // B[n][k] = W_lin[n][k]
        v0 = W_lin[n * CH + k0 + 2 * t];
        v1 = W_lin[n * CH + k0 + 2 * t + 1];
        v2 = W_lin[n * CH + k0 + 2 * t + 8];
        v3 = W_lin[n * CH + k0 + 2 * t + 9];
    } else {                             // B[n][k] = Wm[k][n]
        const float* Wm = (m == 1) ? Wm1 : Wm2;
        v0 = Wm[(k0 + 2 * t) * CH + n];
        v1 = Wm[(k0 + 2 * t + 1) * CH + n];
        v2 = Wm[(k0 + 2 * t + 8) * CH + n];
        v3 = Wm[(k0 + 2 * t + 9) * CH + n];
    }
    uint32_t b0h, b0l, b1h, b1l;
    split_h2(v0, v1, b0h, b0l);
    split_h2(v2, v3, b1h, b1l);
    uint4 v = make_uint4(b0h, b1h, b0l, b1l);
    if (m == 0) g_Hp0[r] = v; else if (m == 1) g_Hp1[r] = v; else g_Hp2[r] = v;
}

// ---------------------------------------------------------------------------
// fp16-split warp-MMA GEMM (m16n8k16): 3 HMMA per (j, K=16).
// ---------------------------------------------------------------------------
__device__ __forceinline__ void gemm_h2(const float* __restrict__ As,
                                        const uint4* __restrict__ P,
                                        float* acc, int m0, int lane)
{
    const int g = lane >> 2, t = lane & 3;
    const float* r0 = As + (m0 + g) * TS + 2 * t;
    const float* r1 = As + (m0 + g + 8) * TS + 2 * t;
    #pragma unroll 1
    for (int kq = 0; kq < 8; kq++) {
        const int k0 = kq * 16;
        float2 x0 = *reinterpret_cast<const float2*>(r0 + k0);
        float2 x1 = *reinterpret_cast<const float2*>(r1 + k0);
        float2 x2 = *reinterpret_cast<const float2*>(r0 + k0 + 8);
        float2 x3 = *reinterpret_cast<const float2*>(r1 + k0 + 8);
        uint32_t ah[4], al[4];
        split_h2(x0.x, x0.y, ah[0], al[0]);
        split_h2(x1.x, x1.y, ah[1], al[1]);
        split_h2(x2.x, x2.y, ah[2], al[2]);
        split_h2(x3.x, x3.y, ah[3], al[3]);
        #pragma unroll
        for (int j = 0; j < 16; j++) {
            uint4 w = __ldg(P + ((j << 3) + kq) * 32 + lane);
            float* c = acc + j * 4;
            MMH(c, ah, w.x, w.y);        // ahi * bhi
            MMH(c, al, w.x, w.y);        // alo * bhi
            MMH(c, ah, w.z, w.w);        // ahi * blo
        }
    }
}

// ---------------------------------------------------------------------------
// h = features @ W_lin^T, emitted as fp16 pairs into g_h2.
// ---------------------------------------------------------------------------
__global__ __launch_bounds__(256, 2)
void node_linear_kernel(const float* __restrict__ feat)
{
    extern __shared__ float sm[];
    float* As = sm;                       // [128][TS]
    const int tid = threadIdx.x;
    const int lane = tid & 31;
    const int m0 = (tid >> 5) * 16;
    const int n0 = blockIdx.x * 128;

    for (int i = tid; i < 128 * 32; i += 256) {
        int r = i >> 5, k4 = i & 31;
        int n = n0 + r;
        float4 v = make_float4(0.f, 0.f, 0.f, 0.f);
        if (n < NN) v = reinterpret_cast<const float4*>(feat)[(size_t)n * 32 + k4];
        *reinterpret_cast<float4*>(As + r * TS + k4 * 4) = v;
    }
    __syncthreads();

    float acc[64];
    #pragma unroll
    for (int i = 0; i < 64; i++) acc[i] = 0.f;
    gemm_h2(As, g_Hp0, acc, m0, lane);
    __syncthreads();

    const int g = lane >> 2, t = lane & 3;
    #pragma unroll
    for (int j = 0; j < 16; j++) {
        int col = j * 8 + 2 * t;
        *reinterpret_cast<float2*>(As + (m0 + g) * TS + col)     = make_float2(acc[j*4+0], acc[j*4+1]);
        *reinterpret_cast<float2*>(As + (m0 + g + 8) * TS + col) = make_float2(acc[j*4+2], acc[j*4+3]);
    }
    __syncthreads();

    for (int i = tid; i < 128 * 16; i += 256) {
        int r = i >> 4, q = i & 15;
        int n = n0 + r;
        if (n < NN) {
            const float* src = As + r * TS + q * 8;
            __half2 h0 = __floats2half2_rn(src[0], src[1]);
            __half2 h1 = __floats2half2_rn(src[2], src[3]);
            __half2 h2 = __floats2half2_rn(src[4], src[5]);
            __half2 h3 = __floats2half2_rn(src[6], src[7]);
            uint4 pk = make_uint4(*(uint32_t*)&h0, *(uint32_t*)&h1,
                                  *(uint32_t*)&h2, *(uint32_t*)&h3);
            reinterpret_cast<uint4*>(g_h2)[(size_t)n * 16 + q] = pk;
        }
    }
}

// ---------------------------------------------------------------------------
// out = ssp(agg @ Wm1 + bm1) @ Wm2 + bm2
// ---------------------------------------------------------------------------
__global__ __launch_bounds__(256, 2)
void out_mlp_kernel(const float* __restrict__ bm1, const float* __restrict__ bm2,
                    float* __restrict__ out)
{
    extern __shared__ float sm[];
    float* As = sm;                       // [128][TS]
    float* bs = sm + 128 * TS;            // [128]
    const int tid = threadIdx.x;
    const int lane = tid & 31;
    const int m0 = (tid >> 5) * 16;
    const int n0 = blockIdx.x * 128;
    const int g = lane >> 2, t = lane & 3;

    if (tid < CH) bs[tid] = bm1[tid];
    for (int i = tid; i < 128 * 32; i += 256) {
        int r = i >> 5, k4 = i & 31;
        int n = n0 + r;
        float4 v = make_float4(0.f, 0.f, 0.f, 0.f);
        if (n < NN) v = reinterpret_cast<const float4*>(g_agg)[(size_t)n * 32 + k4];
        *reinterpret_cast<float4*>(As + r * TS + k4 * 4) = v;
    }
    __syncthreads();

    float acc[64];
    #pragma unroll
    for (int i = 0; i < 64; i++) acc[i] = 0.f;
    gemm_h2(As, g_Hp1, acc, m0, lane);
    __syncthreads();

    #pragma unroll
    for (int j = 0; j < 16; j++) {
        int col = j * 8 + 2 * t;
        float b0 = bs[col], b1 = bs[col + 1];
        *reinterpret_cast<float2*>(As + (m0 + g) * TS + col) =
            make_float2(ssp(acc[j*4+0] + b0), ssp(acc[j*4+1] + b1));
        *reinterpret_cast<float2*>(As + (m0 + g + 8) * TS + col) =
            make_float2(ssp(acc[j*4+2] + b0), ssp(acc[j*4+3] + b1));
    }
    __syncthreads();
    if (tid < CH) bs[tid] = bm2[tid];
    __syncthreads();

    #pragma unroll
    for (int i = 0; i < 64; i++) acc[i] = 0.f;
    gemm_h2(As, g_Hp2, acc, m0, lane);
    __syncthreads();

    #pragma unroll
    for (int j = 0; j < 16; j++) {
        int col = j * 8 + 2 * t;
        float b0 = bs[col], b1 = bs[col + 1];
        *reinterpret_cast<float2*>(As + (m0 + g) * TS + col) =
            make_float2(acc[j*4+0] + b0, acc[j*4+1] + b1);
        *reinterpret_cast<float2*>(As + (m0 + g + 8) * TS + col) =
            make_float2(acc[j*4+2] + b0, acc[j*4+3] + b1);
    }
    __syncthreads();

    for (int i = tid; i < 128 * 32; i += 256) {
        int r = i >> 5, k4 = i & 31;
        int n = n0 + r;
        if (n < NN)
            reinterpret_cast<float4*>(out)[(size_t)n * 32 + k4] =
                *reinterpret_cast<const float4*>(As + r * TS + k4 * 4);
    }
}

// ---------------------------------------------------------------------------
// Build table: ef(r_i), r_i = i*5/NTAB  (proven FFMA tile kernel)
// ---------------------------------------------------------------------------
__global__ __launch_bounds__(256, 1)
void table_kernel(const float* __restrict__ Wf1, const float* __restrict__ bf1,
                  const float* __restrict__ Wf2, const float* __restrict__ bf2)
{
    extern __shared__ float sm[];
    float* Wf1s  = sm;
    float* Wf2s  = Wf1s + FE * CH;
    float* bf1s  = Wf2s + CH * CH;
    float* bf2s  = bf1s + CH;
    float* basis = bf2s + CH;
    float* t1    = basis + 128 * 53;

    const int tid = threadIdx.x;
    const int e0 = blockIdx.x * 128;
    const float H = 5.0f / (float)NTAB;

    for (int i = tid; i < FE * CH; i += 256) Wf1s[i] = Wf1[i];
    for (int i = tid; i < CH * CH; i += 256) Wf2s[i] = Wf2[i];
    if (tid < CH) { bf1s[tid] = bf1[tid]; bf2s[tid] = bf2[tid]; }

    const float delta = 5.0f / 49.0f;
    const float coef  = 2401.0f / 50.0f;
    for (int i = tid; i < 128 * FE; i += 256) {
        int e = i / FE, f = i - e * FE;
        float r = (float)(e0 + e) * H;
        float d = r - delta * (float)f;
        basis[e * 53 + f] = __expf(-coef * d * d);
    }
    __syncthreads();

    const int ei = tid >> 4;
    const int c0 = (tid & 15) * 8;

    float acc[8][8];
    #pragma unroll
    for (int r = 0; r < 8; r++)
        #pragma unroll
        for (int j = 0; j < 8; j++) acc[r][j] = bf1s[c0 + j];

    #pragma unroll 2
    for (int f = 0; f < FE; f++) {
        float a[8];
        #pragma unroll
        for (int r = 0; r < 8; r++) a[r] = basis[(ei * 8 + r) * 53 + f];
        float4 w0 = *reinterpret_cast<const float4*>(Wf1s + f * CH + c0);
        float4 w1 = *reinterpret_cast<const float4*>(Wf1s + f * CH + c0 + 4);
        #pragma unroll
        for (int r = 0; r < 8; r++) { FMA8(acc[r], a[r], w0, w1); }
    }
    #pragma unroll
    for (int r = 0; r < 8; r++)
        #pragma unroll
        for (int j = 0; j < 8; j++)
            t1[(ei * 8 + r) * 130 + c0 + j] = ssp(acc[r][j]);
    __syncthreads();

    #pragma unroll
    for (int r = 0; r < 8; r++)
        #pragma unroll
        for (int j = 0; j < 8; j++) acc[r][j] = bf2s[c0 + j];

    #pragma unroll 2
    for (int k = 0; k < CH; k++) {
        float a[8];
        #pragma unroll
        for (int r = 0; r < 8; r++) a[r] = t1[(ei * 8 + r) * 130 + k];
        float4 w0 = *reinterpret_cast<const float4*>(Wf2s + k * CH + c0);
        float4 w1 = *reinterpret_cast<const float4*>(Wf2s + k * CH + c0 + 4);
        #pragma unroll
        for (int r = 0; r < 8; r++) { FMA8(acc[r], a[r], w0, w1); }
    }

    #pragma unroll
    for (int r = 0; r < 8; r++) {
        int row = e0 + ei * 8 + r;
        if (row <= NTAB) {
            float* dst = g_table + (size_t)row * CH + c0;
            *reinterpret_cast<float4*>(dst)     = make_float4(acc[r][0], acc[r][1], acc[r][2], acc[r][3]);
            *reinterpret_cast<float4*>(dst + 4) = make_float4(acc[r][4], acc[r][5], acc[r][6], acc[r][7]);
        }
    }
}

// ---------------------------------------------------------------------------
// Edge apply (frozen R9 form): warp owns 32 consecutive edges, depth-1
// prefetch; fp16 endpoint table + fp16 h; red.global scatter.
// ---------------------------------------------------------------------------
__global__ __launch_bounds__(256, 8)
void edge_apply_kernel(const float* __restrict__ dist,
                       const int* __restrict__ senders,
                       const int* __restrict__ receivers)
{
    const int lane = threadIdx.x & 31;
    const int warp = (blockIdx.x * blockDim.x + threadIdx.x) >> 5;
    const int nwarps = (gridDim.x * blockDim.x) >> 5;
    const float SCALE = (float)NTAB / 5.0f;
    const unsigned FULL = 0xFFFFFFFFu;

    for (int c = warp; c < NCHUNK; c += nwarps) {
        const int e0 = c << 5;
        float dl = __ldg(dist + e0 + lane);
        int   sl = __ldg(senders + e0 + lane);
        int   rl = __ldg(receivers + e0 + lane);

        float d0 = __shfl_sync(FULL, dl, 0);
        int   s0 = __shfl_sync(FULL, sl, 0);
        float u = d0 * SCALE;
        int   i = (int)u;  i = i < 0 ? 0 : (i > NTAB - 1 ? NTAB - 1 : i);
        float fcur = u - (float)i;
        uint4 tw = __ldg(reinterpret_cast<const uint4*>(
            g_tab2 + (size_t)i * CH) + lane);
        uint2 hw = __ldg(reinterpret_cast<const uint2*>(g_h2 + (size_t)s0 * 64) + lane);

        #pragma unroll 1
        for (int k = 0; k < 32; k++) {
            const int kn = (k + 1 < 32) ? k + 1 : 31;
            float dn = __shfl_sync(FULL, dl, kn);
            int   sn = __shfl_sync(FULL, sl, kn);
            float un = dn * SCALE;
            int   in = (int)un;  in = in < 0 ? 0 : (in > NTAB - 1 ? NTAB - 1 : in);
            float fn = un - (float)in;
            uint4 twn = __ldg(reinterpret_cast<const uint4*>(
                g_tab2 + (size_t)in * CH) + lane);
            uint2 hwn = __ldg(reinterpret_cast<const uint2*>(g_h2 + (size_t)sn * 64) + lane);

            int rk = __shfl_sync(FULL, rl, k);
            float2 p0 = __half22float2(*reinterpret_cast<__half2*>(&tw.x));
            float2 p1 = __half22float2(*reinterpret_cast<__half2*>(&tw.y));
            float2 p2 = __half22float2(*reinterpret_cast<__half2*>(&tw.z));
            float2 p3 = __half22float2(*reinterpret_cast<__half2*>(&tw.w));
            float2 h01 = __half22float2(*reinterpret_cast<__half2*>(&hw.x));
            float2 h23 = __half22float2(*reinterpret_cast<__half2*>(&hw.y));
            float4 m;
            m.x = fmaf(fcur, p0.y - p0.x, p0.x) * h01.x;
            m.y = fmaf(fcur, p1.y - p1.x, p1.x) * h01.y;
            m.z = fmaf(fcur, p2.y - p2.x, p2.x) * h23.x;
            m.w = fmaf(fcur, p3.y - p3.x, p3.x) * h23.y;
            red_add_v4(g_agg + (size_t)rk * CH + lane * 4, m);

            tw = twn; hw = hwn; fcur = fn;
        }
    }
}

// ---------------------------------------------------------------------------
extern "C" void kernel_launch(void* const* d_in, const int* in_sizes, int n_in,
                              void* d_out, int out_size)
{
    const float* features = (const float*)d_in[0];
    const float* dist     = (const float*)d_in[1];
    const float* W_lin    = (const float*)d_in[2];
    const float* Wf1      = (const float*)d_in[3];
    const float* bf1      = (const float*)d_in[4];
    const float* Wf2      = (const float*)d_in[5];
    const float* bf2      = (const float*)d_in[6];
    const float* Wm1      = (const float*)d_in[7];
    const float* bm1      = (const float*)d_in[8];
    const float* Wm2      = (const float*)d_in[9];
    const float* bm2      = (const float*)d_in[10];
    const int*   senders   = (const int*)d_in[11];
    const int*   receivers = (const int*)d_in[12];
    float* out = (float*)d_out;

    const int smemA = 128 * TS * 4;
    const int smemT = (FE * CH + CH * CH + 2 * CH + 128 * 53 + 128 * 130) * 4;
    const int smemC = (128 * TS + CH) * 4;

    cudaFuncSetAttribute(node_linear_kernel, cudaFuncAttributeMaxDynamicSharedMemorySize, smemA);
    cudaFuncSetAttribute(table_kernel,       cudaFuncAttributeMaxDynamicSharedMemorySize, smemT);
    cudaFuncSetAttribute(out_mlp_kernel,     cudaFuncAttributeMaxDynamicSharedMemorySize, smemC);

    // Fork a side stream for the table chain (+agg zero) so it overlaps the
    // weight-pack + node-linear chain. Event fork/join keeps this a single
    // connected capture graph. Streams/events are created per call and
    // intentionally not destroyed during an active capture (few calls total).
    cudaStream_t s2;
    cudaStreamCreateWithFlags(&s2, cudaStreamNonBlocking);
    cudaEvent_t eFork, eJoin;
    cudaEventCreateWithFlags(&eFork, cudaEventDisableTiming);
    cudaEventCreateWithFlags(&eJoin, cudaEventDisableTiming);

    cudaEventRecord(eFork, 0);
    cudaStreamWaitEvent(s2, eFork, 0);

    // side chain: zero agg, build fp32 table, convert to fp16 endpoint table
    zero_agg_kernel<<<1024, 256, 0, s2>>>();
    table_kernel<<<(NTAB + 1 + 127) / 128, 256, smemT, s2>>>(Wf1, bf1, Wf2, bf2);
    tab2_kernel<<<(NTAB * CH + 255) / 256, 256, 0, s2>>>();
    cudaEventRecord(eJoin, s2);

    // main chain: pack weights, node linear -> g_h2
    prep_pack_kernel<<<48, 256>>>(W_lin, Wm1, Wm2);
    node_linear_kernel<<<(NN + 127) / 128, 256, smemA>>>(features);

    // join, then the dependent tail
    cudaStreamWaitEvent(0, eJoin, 0);
    edge_apply_kernel<<<2048, 256>>>(dist, senders, receivers);
    out_mlp_kernel<<<(NN + 127) / 128, 256, smemC>>>(bm1, bm2, out);
}

// round 15
// speedup vs baseline: 1.7703x; 1.1338x over previous
#include <cuda_runtime.h>
#include <cuda_fp16.h>
#include <math.h>
#include <stdint.h>

#define NN 50000
#define NE 1600000
#define CH 128
#define FE 50
#define TS 132
#define NTAB 1024
#define NCHUNK (NE / 32)

__device__ __half2 g_h2[(size_t)NN * 64];            // h in fp16, packed pairs
__device__ float g_agg[(size_t)NN * CH];
__device__ float g_table[(size_t)(NTAB + 1) * CH];
__device__ __half2 g_tab2[(size_t)NTAB * CH];
// fp16-split fragment-packed weights: [j(16)][kq(8)][lane(32)] uint4 = (b0hi,b1hi,b0lo,b1lo)
__device__ uint4 g_Hp0[4096];    // W_lin
__device__ uint4 g_Hp1[4096];    // Wm1
__device__ uint4 g_Hp2[4096];    // Wm2

__device__ __forceinline__ float ssp(float x) {
    return fmaxf(x, 0.0f) + log1pf(__expf(-fabsf(x))) - 0.69314718055994530942f;
}
__device__ __forceinline__ void red_add_v4(float* addr, float4 v) {
    asm volatile("red.global.add.v4.f32 [%0], {%1,%2,%3,%4};"
                 :: "l"(addr), "f"(v.x), "f"(v.y), "f"(v.z), "f"(v.w) : "memory");
}
__device__ __forceinline__ void split_h2(float x, float y, uint32_t& hi, uint32_t& lo) {
    __half2 h = __floats2half2_rn(x, y);
    float2 hb = __half22float2(h);
    __half2 l = __floats2half2_rn(x - hb.x, y - hb.y);
    hi = *reinterpret_cast<uint32_t*>(&h);
    lo = *reinterpret_cast<uint32_t*>(&l);
}
#define MMH(c, a, b0, b1)                                                     \
    asm volatile("mma.sync.aligned.m16n8k16.row.col.f32.f16.f16.f32 "         \
                 "{%0,%1,%2,%3}, {%4,%5,%6,%7}, {%8,%9}, {%0,%1,%2,%3};"      \
                 : "+f"((c)[0]), "+f"((c)[1]), "+f"((c)[2]), "+f"((c)[3])     \
                 : "r"((a)[0]), "r"((a)[1]), "r"((a)[2]), "r"((a)[3]),        \
                   "r"(b0), "r"(b1));

#define FMA8(ar, av, w0, w1)                 \
    ar[0] = fmaf(av, w0.x, ar[0]);           \
    ar[1] = fmaf(av, w0.y, ar[1]);           \
    ar[2] = fmaf(av, w0.z, ar[2]);           \
    ar[3] = fmaf(av, w0.w, ar[3]);           \
    ar[4] = fmaf(av, w1.x, ar[4]);           \
    ar[5] = fmaf(av, w1.y, ar[5]);           \
    ar[6] = fmaf(av, w1.z, ar[6]);           \
    ar[7] = fmaf(av, w1.w, ar[7]);

// ---------------------------------------------------------------------------
__global__ void zero_agg_kernel() {
    size_t i = (size_t)blockIdx.x * blockDim.x + threadIdx.x;
    size_t stride = (size_t)gridDim.x * blockDim.x;
    float4* p = reinterpret_cast<float4*>(g_agg);
    const size_t n4 = (size_t)NN * CH / 4;
    float4 z = make_float4(0.f, 0.f, 0.f, 0.f);
    for (; i < n4; i += stride) p[i] = z;
}

__global__ void tab2_kernel() {
    int idx = blockIdx.x * blockDim.x + threadIdx.x;
    if (idx < NTAB * CH) {
        int i = idx >> 7, c = idx & 127;
        float a = g_table[(size_t)i * CH + c];
        float b = g_table[(size_t)(i + 1) * CH + c];
        g_tab2[(size_t)i * CH + c] = __floats2half2_rn(a, b);
    }
}

// Pack weights into m16n8k16 fp16-split fragment order.
__global__ void prep_pack_kernel(const float* __restrict__ W_lin,
                                 const float* __restrict__ Wm1,
                                 const float* __restrict__ Wm2)
{
    int idx = blockIdx.x * blockDim.x + threadIdx.x;
    if (idx >= 3 * 4096) return;
    int m = idx / 4096, r = idx - m * 4096;
    int lane = r & 31, jk = r >> 5;
    int kq = jk & 7, j = jk >> 3;
    int g = lane >> 2, t = lane & 3;
    int n = j * 8 + g, k0 = kq * 16;

    float v0, v1, v2, v3;
    if (m == 0) {                        // B[n][k] = W_lin[n][k]
        v0 = W_lin[n * CH + k0 + 2 * t];
        v1 = W_lin[n * CH + k0 + 2 * t + 1];
        v2 = W_lin[n * CH + k0 + 2 * t + 8];
        v3 = W_lin[n * CH + k0 + 2 * t + 9];
    } else {                             // B[n][k] = Wm[k][n]
        const float* Wm = (m == 1) ? Wm1 : Wm2;
        v0 = Wm[(k0 + 2 * t) * CH + n];
        v1 = Wm[(k0 + 2 * t + 1) * CH + n];
        v2 = Wm[(k0 + 2 * t + 8) * CH + n];
        v3 = Wm[(k0 + 2 * t + 9) * CH + n];
    }
    uint32_t b0h, b0l, b1h, b1l;
    split_h2(v0, v1, b0h, b0l);
    split_h2(v2, v3, b1h, b1l);
    uint4 v = make_uint4(b0h, b1h, b0l, b1l);
    if (m == 0) g_Hp0[r] = v; else if (m == 1) g_Hp1[r] = v; else g_Hp2[r] = v;
}

// ---------------------------------------------------------------------------
// fp16-split warp-MMA GEMM (m16n8k16): 3 HMMA per (j, K=16).
// ---------------------------------------------------------------------------
__device__ __forceinline__ void gemm_h2(const float* __restrict__ As,
                                        const uint4* __restrict__ P,
                                        float* acc, int m0, int lane)
{
    const int g = lane >> 2, t = lane & 3;
    const float* r0 = As + (m0 + g) * TS + 2 * t;
    const float* r1 = As + (m0 + g + 8) * TS + 2 * t;
    #pragma unroll 1
    for (int kq = 0; kq < 8; kq++) {
        const int k0 = kq * 16;
        float2 x0 = *reinterpret_cast<const float2*>(r0 + k0);
        float2 x1 = *reinterpret_cast<const float2*>(r1 + k0);
        float2 x2 = *reinterpret_cast<const float2*>(r0 + k0 + 8);
        float2 x3 = *reinterpret_cast<const float2*>(r1 + k0 + 8);
        uint32_t ah[4], al[4];
        split_h2(x0.x, x0.y, ah[0], al[0]);
        split_h2(x1.x, x1.y, ah[1], al[1]);
        split_h2(x2.x, x2.y, ah[2], al[2]);
        split_h2(x3.x, x3.y, ah[3], al[3]);
        #pragma unroll
        for (int j = 0; j < 16; j++) {
            uint4 w = __ldg(P + ((j << 3) + kq) * 32 + lane);
            float* c = acc + j * 4;
            MMH(c, ah, w.x, w.y);        // ahi * bhi
            MMH(c, al, w.x, w.y);        // alo * bhi
            MMH(c, ah, w.z, w.w);        // ahi * blo
        }
    }
}

// ---------------------------------------------------------------------------
// h = features @ W_lin^T, emitted as fp16 pairs into g_h2.
// ---------------------------------------------------------------------------
__global__ __launch_bounds__(256, 2)
void node_linear_kernel(const float* __restrict__ feat)
{
    extern __shared__ float sm[];
    float* As = sm;                       // [128][TS]
    const int tid = threadIdx.x;
    const int lane = tid & 31;
    const int m0 = (tid >> 5) * 16;
    const int n0 = blockIdx.x * 128;

    for (int i = tid; i < 128 * 32; i += 256) {
        int r = i >> 5, k4 = i & 31;
        int n = n0 + r;
        float4 v = make_float4(0.f, 0.f, 0.f, 0.f);
        if (n < NN) v = reinterpret_cast<const float4*>(feat)[(size_t)n * 32 + k4];
        *reinterpret_cast<float4*>(As + r * TS + k4 * 4) = v;
    }
    __syncthreads();

    float acc[64];
    #pragma unroll
    for (int i = 0; i < 64; i++) acc[i] = 0.f;
    gemm_h2(As, g_Hp0, acc, m0, lane);
    __syncthreads();

    const int g = lane >> 2, t = lane & 3;
    #pragma unroll
    for (int j = 0; j < 16; j++) {
        int col = j * 8 + 2 * t;
        *reinterpret_cast<float2*>(As + (m0 + g) * TS + col)     = make_float2(acc[j*4+0], acc[j*4+1]);
        *reinterpret_cast<float2*>(As + (m0 + g + 8) * TS + col) = make_float2(acc[j*4+2], acc[j*4+3]);
    }
    __syncthreads();

    for (int i = tid; i < 128 * 16; i += 256) {
        int r = i >> 4, q = i & 15;
        int n = n0 + r;
        if (n < NN) {
            const float* src = As + r * TS + q * 8;
            __half2 h0 = __floats2half2_rn(src[0], src[1]);
            __half2 h1 = __floats2half2_rn(src[2], src[3]);
            __half2 h2 = __floats2half2_rn(src[4], src[5]);
            __half2 h3 = __floats2half2_rn(src[6], src[7]);
            uint4 pk = make_uint4(*(uint32_t*)&h0, *(uint32_t*)&h1,
                                  *(uint32_t*)&h2, *(uint32_t*)&h3);
            reinterpret_cast<uint4*>(g_h2)[(size_t)n * 16 + q] = pk;
        }
    }
}

// ---------------------------------------------------------------------------
// out = ssp(agg @ Wm1 + bm1) @ Wm2 + bm2 — register-resident double GEMM.
// ---------------------------------------------------------------------------
__global__ __launch_bounds__(128, 3)
void out_mlp_kernel(const float* __restrict__ bm1, const float* __restrict__ bm2,
                    float* __restrict__ out)
{
    extern __shared__ float sm[];
    float* As  = sm;                      // [64][TS]
    float* bs1 = sm + 64 * TS;            // [128]
    float* bs2 = bs1 + CH;                // [128]
    const int tid = threadIdx.x;
    const int lane = tid & 31;
    const int m0 = (tid >> 5) * 16;
    const int n0 = blockIdx.x * 64;
    const int g = lane >> 2, t = lane & 3;

    if (tid < CH) { bs1[tid] = bm1[tid]; bs2[tid] = bm2[tid]; }
    for (int i = tid; i < 64 * 32; i += 128) {
        int r = i >> 5, k4 = i & 31;
        int n = n0 + r;
        float4 v = make_float4(0.f, 0.f, 0.f, 0.f);
        if (n < NN) v = reinterpret_cast<const float4*>(g_agg)[(size_t)n * 32 + k4];
        *reinterpret_cast<float4*>(As + r * TS + k4 * 4) = v;
    }
    __syncthreads();

    float acc1[64];
    #pragma unroll
    for (int i = 0; i < 64; i++) acc1[i] = 0.f;
    gemm_h2(As, g_Hp1, acc1, m0, lane);

    float acc2[64];
    #pragma unroll
    for (int i = 0; i < 64; i++) acc2[i] = 0.f;
    #pragma unroll 1
    for (int kq = 0; kq < 8; kq++) {
        const int jj = 2 * kq;
        float b0 = bs1[jj * 8 + 2 * t],       b1 = bs1[jj * 8 + 2 * t + 1];
        float b2 = bs1[(jj + 1) * 8 + 2 * t], b3 = bs1[(jj + 1) * 8 + 2 * t + 1];
        uint32_t ah[4], al[4];
        split_h2(ssp(acc1[jj*4+0] + b0),     ssp(acc1[jj*4+1] + b1),     ah[0], al[0]);
        split_h2(ssp(acc1[jj*4+2] + b0),     ssp(acc1[jj*4+3] + b1),     ah[1], al[1]);
        split_h2(ssp(acc1[(jj+1)*4+0] + b2), ssp(acc1[(jj+1)*4+1] + b3), ah[2], al[2]);
        split_h2(ssp(acc1[(jj+1)*4+2] + b2), ssp(acc1[(jj+1)*4+3] + b3), ah[3], al[3]);
        #pragma unroll
        for (int j = 0; j < 16; j++) {
            uint4 w = __ldg(g_Hp2 + ((j << 3) + kq) * 32 + lane);
            float* c = acc2 + j * 4;
            MMH(c, ah, w.x, w.y);
            MMH(c, al, w.x, w.y);
            MMH(c, ah, w.z, w.w);
        }
    }

    #pragma unroll
    for (int j = 0; j < 16; j++) {
        int col = j * 8 + 2 * t;
        float b0 = bs2[col], b1 = bs2[col + 1];
        *reinterpret_cast<float2*>(As + (m0 + g) * TS + col) =
            make_float2(acc2[j*4+0] + b0, acc2[j*4+1] + b1);
        *reinterpret_cast<float2*>(As + (m0 + g + 8) * TS + col) =
            make_float2(acc2[j*4+2] + b0, acc2[j*4+3] + b1);
    }
    __syncthreads();

    for (int i = tid; i < 64 * 32; i += 128) {
        int r = i >> 5, k4 = i & 31;
        int n = n0 + r;
        if (n < NN)
            reinterpret_cast<float4*>(out)[(size_t)n * 32 + k4] =
                *reinterpret_cast<const float4*>(As + r * TS + k4 * 4);
    }
}

// ---------------------------------------------------------------------------
// Build table: ef(r_i), r_i = i*5/NTAB  (proven FFMA tile kernel)
// ---------------------------------------------------------------------------
__global__ __launch_bounds__(256, 1)
void table_kernel(const float* __restrict__ Wf1, const float* __restrict__ bf1,
                  const float* __restrict__ Wf2, const float* __restrict__ bf2)
{
    extern __shared__ float sm[];
    float* Wf1s  = sm;
    float* Wf2s  = Wf1s + FE * CH;
    float* bf1s  = Wf2s + CH * CH;
    float* bf2s  = bf1s + CH;
    float* basis = bf2s + CH;
    float* t1    = basis + 128 * 53;

    const int tid = threadIdx.x;
    const int e0 = blockIdx.x * 128;
    const float H = 5.0f / (float)NTAB;

    for (int i = tid; i < FE * CH; i += 256) Wf1s[i] = Wf1[i];
    for (int i = tid; i < CH * CH; i += 256) Wf2s[i] = Wf2[i];
    if (tid < CH) { bf1s[tid] = bf1[tid]; bf2s[tid] = bf2[tid]; }

    const float delta = 5.0f / 49.0f;
    const float coef  = 2401.0f / 50.0f;
    for (int i = tid; i < 128 * FE; i += 256) {
        int e = i / FE, f = i - e * FE;
        float r = (float)(e0 + e) * H;
        float d = r - delta * (float)f;
        basis[e * 53 + f] = __expf(-coef * d * d);
    }
    __syncthreads();

    const int ei = tid >> 4;
    const int c0 = (tid & 15) * 8;

    float acc[8][8];
    #pragma unroll
    for (int r = 0; r < 8; r++)
        #pragma unroll
        for (int j = 0; j < 8; j++) acc[r][j] = bf1s[c0 + j];

    #pragma unroll 2
    for (int f = 0; f < FE; f++) {
        float a[8];
        #pragma unroll
        for (int r = 0; r < 8; r++) a[r] = basis[(ei * 8 + r) * 53 + f];
        float4 w0 = *reinterpret_cast<const float4*>(Wf1s + f * CH + c0);
        float4 w1 = *reinterpret_cast<const float4*>(Wf1s + f * CH + c0 + 4);
        #pragma unroll
        for (int r = 0; r < 8; r++) { FMA8(acc[r], a[r], w0, w1); }
    }
    #pragma unroll
    for (int r = 0; r < 8; r++)
        #pragma unroll
        for (int j = 0; j < 8; j++)
            t1[(ei * 8 + r) * 130 + c0 + j] = ssp(acc[r][j]);
    __syncthreads();

    #pragma unroll
    for (int r = 0; r < 8; r++)
        #pragma unroll
        for (int j = 0; j < 8; j++) acc[r][j] = bf2s[c0 + j];

    #pragma unroll 2
    for (int k = 0; k < CH; k++) {
        float a[8];
        #pragma unroll
        for (int r = 0; r < 8; r++) a[r] = t1[(ei * 8 + r) * 130 + k];
        float4 w0 = *reinterpret_cast<const float4*>(Wf2s + k * CH + c0);
        float4 w1 = *reinterpret_cast<const float4*>(Wf2s + k * CH + c0 + 4);
        #pragma unroll
        for (int r = 0; r < 8; r++) { FMA8(acc[r], a[r], w0, w1); }
    }

    #pragma unroll
    for (int r = 0; r < 8; r++) {
        int row = e0 + ei * 8 + r;
        if (row <= NTAB) {
            float* dst = g_table + (size_t)row * CH + c0;
            *reinterpret_cast<float4*>(dst)     = make_float4(acc[r][0], acc[r][1], acc[r][2], acc[r][3]);
            *reinterpret_cast<float4*>(dst + 4) = make_float4(acc[r][4], acc[r][5], acc[r][6], acc[r][7]);
        }
    }
}

// ---------------------------------------------------------------------------
// Edge apply (frozen R9 form): warp owns 32 consecutive edges, depth-1
// prefetch; fp16 endpoint table (now L1-resident-ish) + fp16 h; red scatter.
// ---------------------------------------------------------------------------
__global__ __launch_bounds__(256, 8)
void edge_apply_kernel(const float* __restrict__ dist,
                       const int* __restrict__ senders,
                       const int* __restrict__ receivers)
{
    const int lane = threadIdx.x & 31;
    const int warp = (blockIdx.x * blockDim.x + threadIdx.x) >> 5;
    const int nwarps = (gridDim.x * blockDim.x) >> 5;
    const float SCALE = (float)NTAB / 5.0f;
    const unsigned FULL = 0xFFFFFFFFu;

    for (int c = warp; c < NCHUNK; c += nwarps) {
        const int e0 = c << 5;
        float dl = __ldg(dist + e0 + lane);
        int   sl = __ldg(senders + e0 + lane);
        int   rl = __ldg(receivers + e0 + lane);

        float d0 = __shfl_sync(FULL, dl, 0);
        int   s0 = __shfl_sync(FULL, sl, 0);
        float u = d0 * SCALE;
        int   i = (int)u;  i = i < 0 ? 0 : (i > NTAB - 1 ? NTAB - 1 : i);
        float fcur = u - (float)i;
        uint4 tw = __ldg(reinterpret_cast<const uint4*>(
            g_tab2 + (size_t)i * CH) + lane);
        uint2 hw = __ldg(reinterpret_cast<const uint2*>(g_h2 + (size_t)s0 * 64) + lane);

        #pragma unroll 1
        for (int k = 0; k < 32; k++) {
            const int kn = (k + 1 < 32) ? k + 1 : 31;
            float dn = __shfl_sync(FULL, dl, kn);
            int   sn = __shfl_sync(FULL, sl, kn);
            float un = dn * SCALE;
            int   in = (int)un;  in = in < 0 ? 0 : (in > NTAB - 1 ? NTAB - 1 : in);
            float fn = un - (float)in;
            uint4 twn = __ldg(reinterpret_cast<const uint4*>(
                g_tab2 + (size_t)in * CH) + lane);
            uint2 hwn = __ldg(reinterpret_cast<const uint2*>(g_h2 + (size_t)sn * 64) + lane);

            int rk = __shfl_sync(FULL, rl, k);
            float2 p0 = __half22float2(*reinterpret_cast<__half2*>(&tw.x));
            float2 p1 = __half22float2(*reinterpret_cast<__half2*>(&tw.y));
            float2 p2 = __half22float2(*reinterpret_cast<__half2*>(&tw.z));
            float2 p3 = __half22float2(*reinterpret_cast<__half2*>(&tw.w));
            float2 h01 = __half22float2(*reinterpret_cast<__half2*>(&hw.x));
            float2 h23 = __half22float2(*reinterpret_cast<__half2*>(&hw.y));
            float4 m;
            m.x = fmaf(fcur, p0.y - p0.x, p0.x) * h01.x;
            m.y = fmaf(fcur, p1.y - p1.x, p1.x) * h01.y;
            m.z = fmaf(fcur, p2.y - p2.x, p2.x) * h23.x;
            m.w = fmaf(fcur, p3.y - p3.x, p3.x) * h23.y;
            red_add_v4(g_agg + (size_t)rk * CH + lane * 4, m);

            tw = twn; hw = hwn; fcur = fn;
        }
    }
}

// ---------------------------------------------------------------------------
extern "C" void kernel_launch(void* const* d_in, const int* in_sizes, int n_in,
                              void* d_out, int out_size)
{
    const float* features = (const float*)d_in[0];
    const float* dist     = (const float*)d_in[1];
    const float* W_lin    = (const float*)d_in[2];
    const float* Wf1      = (const float*)d_in[3];
    const float* bf1      = (const float*)d_in[4];
    const float* Wf2      = (const float*)d_in[5];
    const float* bf2      = (const float*)d_in[6];
    const float* Wm1      = (const float*)d_in[7];
    const float* bm1      = (const float*)d_in[8];
    const float* Wm2      = (const float*)d_in[9];
    const float* bm2      = (const float*)d_in[10];
    const int*   senders   = (const int*)d_in[11];
    const int*   receivers = (const int*)d_in[12];
    float* out = (float*)d_out;

    const int smemA = 128 * TS * 4;
    const int smemT = (FE * CH + CH * CH + 2 * CH + 128 * 53 + 128 * 130) * 4;
    const int smemC = (64 * TS + 2 * CH) * 4;

    // One-time resources (created on the first, uncaptured correctness call —
    // before the harness's pre-capture memory baseline; reused forever after,
    // so captured replays are allocation-free).
    static cudaStream_t s2 = nullptr, s3 = nullptr;
    static cudaEvent_t eFork = nullptr, eJoin2 = nullptr, eJoin3 = nullptr;
    static bool init_done = false;
    if (!init_done) {
        cudaStreamCreateWithFlags(&s2, cudaStreamNonBlocking);
        cudaStreamCreateWithFlags(&s3, cudaStreamNonBlocking);
        cudaEventCreateWithFlags(&eFork,  cudaEventDisableTiming);
        cudaEventCreateWithFlags(&eJoin2, cudaEventDisableTiming);
        cudaEventCreateWithFlags(&eJoin3, cudaEventDisableTiming);
        cudaFuncSetAttribute(node_linear_kernel, cudaFuncAttributeMaxDynamicSharedMemorySize, smemA);
        cudaFuncSetAttribute(table_kernel,       cudaFuncAttributeMaxDynamicSharedMemorySize, smemT);
        cudaFuncSetAttribute(out_mlp_kernel,     cudaFuncAttributeMaxDynamicSharedMemorySize, smemC);
        init_done = true;
    }

    cudaEventRecord(eFork, 0);
    cudaStreamWaitEvent(s2, eFork, 0);
    cudaStreamWaitEvent(s3, eFork, 0);

    // s2: build fp32 table, convert to fp16 endpoint table
    table_kernel<<<(NTAB + 1 + 127) / 128, 256, smemT, s2>>>(Wf1, bf1, Wf2, bf2);
    tab2_kernel<<<(NTAB * CH + 255) / 256, 256, 0, s2>>>();
    cudaEventRecord(eJoin2, s2);

    // s3: zero the aggregation buffer
    zero_agg_kernel<<<1024, 256, 0, s3>>>();
    cudaEventRecord(eJoin3, s3);

    // main: pack weights, node linear -> g_h2
    prep_pack_kernel<<<48, 256>>>(W_lin, Wm1, Wm2);
    node_linear_kernel<<<(NN + 127) / 128, 256, smemA>>>(features);

    cudaStreamWaitEvent(0, eJoin2, 0);
    cudaStreamWaitEvent(0, eJoin3, 0);
    edge_apply_kernel<<<2048, 256>>>(dist, senders, receivers);
    out_mlp_kernel<<<(NN + 63) / 64, 128, smemC>>>(bm1, bm2, out);
}

// round 16
// speedup vs baseline: 1.8592x; 1.0502x over previous
#include <cuda_runtime.h>
#include <cuda_fp16.h>
#include <math.h>
#include <stdint.h>

#define NN 50000
#define NE 1600000
#define CH 128
#define FE 50
#define TS 132
#define NTAB 256
#define NCHUNK (NE / 32)

__device__ __half2 g_h2[(size_t)NN * 64];            // h in fp16, packed pairs
__device__ float g_agg[(size_t)NN * CH];
__device__ float g_table[(size_t)(NTAB + 1) * CH];
__device__ __half2 g_tab2[(size_t)NTAB * CH];
// fp16-split fragment-packed weights: [j(16)][kq(8)][lane(32)] uint4 = (b0hi,b1hi,b0lo,b1lo)
__device__ uint4 g_Hp0[4096];    // W_lin
__device__ uint4 g_Hp1[4096];    // Wm1
__device__ uint4 g_Hp2[4096];    // Wm2

__device__ __forceinline__ float ssp(float x) {
    return fmaxf(x, 0.0f) + log1pf(__expf(-fabsf(x))) - 0.69314718055994530942f;
}
__device__ __forceinline__ void red_add_v4(float* addr, float4 v) {
    asm volatile("red.global.add.v4.f32 [%0], {%1,%2,%3,%4};"
                 :: "l"(addr), "f"(v.x), "f"(v.y), "f"(v.z), "f"(v.w) : "memory");
}
__device__ __forceinline__ void split_h2(float x, float y, uint32_t& hi, uint32_t& lo) {
    __half2 h = __floats2half2_rn(x, y);
    float2 hb = __half22float2(h);
    __half2 l = __floats2half2_rn(x - hb.x, y - hb.y);
    hi = *reinterpret_cast<uint32_t*>(&h);
    lo = *reinterpret_cast<uint32_t*>(&l);
}
#define MMH(c, a, b0, b1)                                                     \
    asm volatile("mma.sync.aligned.m16n8k16.row.col.f32.f16.f16.f32 "         \
                 "{%0,%1,%2,%3}, {%4,%5,%6,%7}, {%8,%9}, {%0,%1,%2,%3};"      \
                 : "+f"((c)[0]), "+f"((c)[1]), "+f"((c)[2]), "+f"((c)[3])     \
                 : "r"((a)[0]), "r"((a)[1]), "r"((a)[2]), "r"((a)[3]),        \
                   "r"(b0), "r"(b1));

#define FMA8(ar, av, w0, w1)                 \
    ar[0] = fmaf(av, w0.x, ar[0]);           \
    ar[1] = fmaf(av, w0.y, ar[1]);           \
    ar[2] = fmaf(av, w0.z, ar[2]);           \
    ar[3] = fmaf(av, w0.w, ar[3]);           \
    ar[4] = fmaf(av, w1.x, ar[4]);           \
    ar[5] = fmaf(av, w1.y, ar[5]);           \
    ar[6] = fmaf(av, w1.z, ar[6]);           \
    ar[7] = fmaf(av, w1.w, ar[7]);

// ---------------------------------------------------------------------------
__global__ void zero_agg_kernel() {
    size_t i = (size_t)blockIdx.x * blockDim.x + threadIdx.x;
    size_t stride = (size_t)gridDim.x * blockDim.x;
    float4* p = reinterpret_cast<float4*>(g_agg);
    const size_t n4 = (size_t)NN * CH / 4;
    float4 z = make_float4(0.f, 0.f, 0.f, 0.f);
    for (; i < n4; i += stride) p[i] = z;
}

__global__ void tab2_kernel() {
    int idx = blockIdx.x * blockDim.x + threadIdx.x;
    if (idx < NTAB * CH) {
        int i = idx >> 7, c = idx & 127;
        float a = g_table[(size_t)i * CH + c];
        float b = g_table[(size_t)(i + 1) * CH + c];
        g_tab2[(size_t)i * CH + c] = __floats2half2_rn(a, b);
    }
}

// Pack weights into m16n8k16 fp16-split fragment order.
__global__ void prep_pack_kernel(const float* __restrict__ W_lin,
                                 const float* __restrict__ Wm1,
                                 const float* __restrict__ Wm2)
{
    int idx = blockIdx.x * blockDim.x + threadIdx.x;
    if (idx >= 3 * 4096) return;
    int m = idx / 4096, r = idx - m * 4096;
    int lane = r & 31, jk = r >> 5;
    int kq = jk & 7, j = jk >> 3;
    int g = lane >> 2, t = lane & 3;
    int n = j * 8 + g, k0 = kq * 16;

    float v0, v1, v2, v3;
    if (m == 0) {                        // B[n][k] = W_lin[n][k]
        v0 = W_lin[n * CH + k0 + 2 * t];
        v1 = W_lin[n * CH + k0 + 2 * t + 1];
        v2 = W_lin[n * CH + k0 + 2 * t + 8];
        v3 = W_lin[n * CH + k0 + 2 * t + 9];
    } else {                             // B[n][k] = Wm[k][n]
        const float* Wm = (m == 1) ? Wm1 : Wm2;
        v0 = Wm[(k0 + 2 * t) * CH + n];
        v1 = Wm[(k0 + 2 * t + 1) * CH + n];
        v2 = Wm[(k0 + 2 * t + 8) * CH + n];
        v3 = Wm[(k0 + 2 * t + 9) * CH + n];
    }
    uint32_t b0h, b0l, b1h, b1l;
    split_h2(v0, v1, b0h, b0l);
    split_h2(v2, v3, b1h, b1l);
    uint4 v = make_uint4(b0h, b1h, b0l, b1l);
    if (m == 0) g_Hp0[r] = v; else if (m == 1) g_Hp1[r] = v; else g_Hp2[r] = v;
}

// ---------------------------------------------------------------------------
// fp16-split warp-MMA GEMM (m16n8k16): 3 HMMA per (j, K=16).
// ---------------------------------------------------------------------------
__device__ __forceinline__ void gemm_h2(const float* __restrict__ As,
                                        const uint4* __restrict__ P,
                                        float* acc, int m0, int lane)
{
    const int g = lane >> 2, t = lane & 3;
    const float* r0 = As + (m0 + g) * TS + 2 * t;
    const float* r1 = As + (m0 + g + 8) * TS + 2 * t;
    #pragma unroll 1
    for (int kq = 0; kq < 8; kq++) {
        const int k0 = kq * 16;
        float2 x0 = *reinterpret_cast<const float2*>(r0 + k0);
        float2 x1 = *reinterpret_cast<const float2*>(r1 + k0);
        float2 x2 = *reinterpret_cast<const float2*>(r0 + k0 + 8);
        float2 x3 = *reinterpret_cast<const float2*>(r1 + k0 + 8);
        uint32_t ah[4], al[4];
        split_h2(x0.x, x0.y, ah[0], al[0]);
        split_h2(x1.x, x1.y, ah[1], al[1]);
        split_h2(x2.x, x2.y, ah[2], al[2]);
        split_h2(x3.x, x3.y, ah[3], al[3]);
        #pragma unroll
        for (int j = 0; j < 16; j++) {
            uint4 w = __ldg(P + ((j << 3) + kq) * 32 + lane);
            float* c = acc + j * 4;
            MMH(c, ah, w.x, w.y);        // ahi * bhi
            MMH(c, al, w.x, w.y);        // alo * bhi
            MMH(c, ah, w.z, w.w);        // ahi * blo
        }
    }
}

// ---------------------------------------------------------------------------
// h = features @ W_lin^T, emitted as fp16 pairs into g_h2.
// ---------------------------------------------------------------------------
__global__ __launch_bounds__(256, 2)
void node_linear_kernel(const float* __restrict__ feat)
{
    extern __shared__ float sm[];
    float* As = sm;                       // [128][TS]
    const int tid = threadIdx.x;
    const int lane = tid & 31;
    const int m0 = (tid >> 5) * 16;
    const int n0 = blockIdx.x * 128;

    for (int i = tid; i < 128 * 32; i += 256) {
        int r = i >> 5, k4 = i & 31;
        int n = n0 + r;
        float4 v = make_float4(0.f, 0.f, 0.f, 0.f);
        if (n < NN) v = reinterpret_cast<const float4*>(feat)[(size_t)n * 32 + k4];
        *reinterpret_cast<float4*>(As + r * TS + k4 * 4) = v;
    }
    __syncthreads();

    float acc[64];
    #pragma unroll
    for (int i = 0; i < 64; i++) acc[i] = 0.f;
    gemm_h2(As, g_Hp0, acc, m0, lane);
    __syncthreads();

    const int g = lane >> 2, t = lane & 3;
    #pragma unroll
    for (int j = 0; j < 16; j++) {
        int col = j * 8 + 2 * t;
        *reinterpret_cast<float2*>(As + (m0 + g) * TS + col)     = make_float2(acc[j*4+0], acc[j*4+1]);
        *reinterpret_cast<float2*>(As + (m0 + g + 8) * TS + col) = make_float2(acc[j*4+2], acc[j*4+3]);
    }
    __syncthreads();

    for (int i = tid; i < 128 * 16; i += 256) {
        int r = i >> 4, q = i & 15;
        int n = n0 + r;
        if (n < NN) {
            const float* src = As + r * TS + q * 8;
            __half2 h0 = __floats2half2_rn(src[0], src[1]);
            __half2 h1 = __floats2half2_rn(src[2], src[3]);
            __half2 h2 = __floats2half2_rn(src[4], src[5]);
            __half2 h3 = __floats2half2_rn(src[6], src[7]);
            uint4 pk = make_uint4(*(uint32_t*)&h0, *(uint32_t*)&h1,
                                  *(uint32_t*)&h2, *(uint32_t*)&h3);
            reinterpret_cast<uint4*>(g_h2)[(size_t)n * 16 + q] = pk;
        }
    }
}

// ---------------------------------------------------------------------------
// out = ssp(agg @ Wm1 + bm1) @ Wm2 + bm2 — register-resident double GEMM.
// ---------------------------------------------------------------------------
__global__ __launch_bounds__(128, 3)
void out_mlp_kernel(const float* __restrict__ bm1, const float* __restrict__ bm2,
                    float* __restrict__ out)
{
    extern __shared__ float sm[];
    float* As  = sm;                      // [64][TS]
    float* bs1 = sm + 64 * TS;            // [128]
    float* bs2 = bs1 + CH;                // [128]
    const int tid = threadIdx.x;
    const int lane = tid & 31;
    const int m0 = (tid >> 5) * 16;
    const int n0 = blockIdx.x * 64;
    const int g = lane >> 2, t = lane & 3;

    if (tid < CH) { bs1[tid] = bm1[tid]; bs2[tid] = bm2[tid]; }
    for (int i = tid; i < 64 * 32; i += 128) {
        int r = i >> 5, k4 = i & 31;
        int n = n0 + r;
        float4 v = make_float4(0.f, 0.f, 0.f, 0.f);
        if (n < NN) v = reinterpret_cast<const float4*>(g_agg)[(size_t)n * 32 + k4];
        *reinterpret_cast<float4*>(As + r * TS + k4 * 4) = v;
    }
    __syncthreads();

    float acc1[64];
    #pragma unroll
    for (int i = 0; i < 64; i++) acc1[i] = 0.f;
    gemm_h2(As, g_Hp1, acc1, m0, lane);

    float acc2[64];
    #pragma unroll
    for (int i = 0; i < 64; i++) acc2[i] = 0.f;
    #pragma unroll 1
    for (int kq = 0; kq < 8; kq++) {
        const int jj = 2 * kq;
        float b0 = bs1[jj * 8 + 2 * t],       b1 = bs1[jj * 8 + 2 * t + 1];
        float b2 = bs1[(jj + 1) * 8 + 2 * t], b3 = bs1[(jj + 1) * 8 + 2 * t + 1];
        uint32_t ah[4], al[4];
        split_h2(ssp(acc1[jj*4+0] + b0),     ssp(acc1[jj*4+1] + b1),     ah[0], al[0]);
        split_h2(ssp(acc1[jj*4+2] + b0),     ssp(acc1[jj*4+3] + b1),     ah[1], al[1]);
        split_h2(ssp(acc1[(jj+1)*4+0] + b2), ssp(acc1[(jj+1)*4+1] + b3), ah[2], al[2]);
        split_h2(ssp(acc1[(jj+1)*4+2] + b2), ssp(acc1[(jj+1)*4+3] + b3), ah[3], al[3]);
        #pragma unroll
        for (int j = 0; j < 16; j++) {
            uint4 w = __ldg(g_Hp2 + ((j << 3) + kq) * 32 + lane);
            float* c = acc2 + j * 4;
            MMH(c, ah, w.x, w.y);
            MMH(c, al, w.x, w.y);
            MMH(c, ah, w.z, w.w);
        }
    }

    #pragma unroll
    for (int j = 0; j < 16; j++) {
        int col = j * 8 + 2 * t;
        float b0 = bs2[col], b1 = bs2[col + 1];
        *reinterpret_cast<float2*>(As + (m0 + g) * TS + col) =
            make_float2(acc2[j*4+0] + b0, acc2[j*4+1] + b1);
        *reinterpret_cast<float2*>(As + (m0 + g + 8) * TS + col) =
            make_float2(acc2[j*4+2] + b0, acc2[j*4+3] + b1);
    }
    __syncthreads();

    for (int i = tid; i < 64 * 32; i += 128) {
        int r = i >> 5, k4 = i & 31;
        int n = n0 + r;
        if (n < NN)
            reinterpret_cast<float4*>(out)[(size_t)n * 32 + k4] =
                *reinterpret_cast<const float4*>(As + r * TS + k4 * 4);
    }
}

// ---------------------------------------------------------------------------
// Build table: ef(r_i), r_i = i*5/NTAB  (proven FFMA tile kernel)
// ---------------------------------------------------------------------------
__global__ __launch_bounds__(256, 1)
void table_kernel(const float* __restrict__ Wf1, const float* __restrict__ bf1,
                  const float* __restrict__ Wf2, const float* __restrict__ bf2)
{
    extern __shared__ float sm[];
    float* Wf1s  = sm;
    float* Wf2s  = Wf1s + FE * CH;
    float* bf1s  = Wf2s + CH * CH;
    float* bf2s  = bf1s + CH;
    float* basis = bf2s + CH;
    float* t1    = basis + 128 * 53;

    const int tid = threadIdx.x;
    const int e0 = blockIdx.x * 128;
    const float H = 5.0f / (float)NTAB;

    for (int i = tid; i < FE * CH; i += 256) Wf1s[i] = Wf1[i];
    for (int i = tid; i < CH * CH; i += 256) Wf2s[i] = Wf2[i];
    if (tid < CH) { bf1s[tid] = bf1[tid]; bf2s[tid] = bf2[tid]; }

    const float delta = 5.0f / 49.0f;
    const float coef  = 2401.0f / 50.0f;
    for (int i = tid; i < 128 * FE; i += 256) {
        int e = i / FE, f = i - e * FE;
        float r = (float)(e0 + e) * H;
        float d = r - delta * (float)f;
        basis[e * 53 + f] = __expf(-coef * d * d);
    }
    __syncthreads();

    const int ei = tid >> 4;
    const int c0 = (tid & 15) * 8;

    float acc[8][8];
    #pragma unroll
    for (int r = 0; r < 8; r++)
        #pragma unroll
        for (int j = 0; j < 8; j++) acc[r][j] = bf1s[c0 + j];

    #pragma unroll 2
    for (int f = 0; f < FE; f++) {
        float a[8];
        #pragma unroll
        for (int r = 0; r < 8; r++) a[r] = basis[(ei * 8 + r) * 53 + f];
        float4 w0 = *reinterpret_cast<const float4*>(Wf1s + f * CH + c0);
        float4 w1 = *reinterpret_cast<const float4*>(Wf1s + f * CH + c0 + 4);
        #pragma unroll
        for (int r = 0; r < 8; r++) { FMA8(acc[r], a[r], w0, w1); }
    }
    #pragma unroll
    for (int r = 0; r < 8; r++)
        #pragma unroll
        for (int j = 0; j < 8; j++)
            t1[(ei * 8 + r) * 130 + c0 + j] = ssp(acc[r][j]);
    __syncthreads();

    #pragma unroll
    for (int r = 0; r < 8; r++)
        #pragma unroll
        for (int j = 0; j < 8; j++) acc[r][j] = bf2s[c0 + j];

    #pragma unroll 2
    for (int k = 0; k < CH; k++) {
        float a[8];
        #pragma unroll
        for (int r = 0; r < 8; r++) a[r] = t1[(ei * 8 + r) * 130 + k];
        float4 w0 = *reinterpret_cast<const float4*>(Wf2s + k * CH + c0);
        float4 w1 = *reinterpret_cast<const float4*>(Wf2s + k * CH + c0 + 4);
        #pragma unroll
        for (int r = 0; r < 8; r++) { FMA8(acc[r], a[r], w0, w1); }
    }

    #pragma unroll
    for (int r = 0; r < 8; r++) {
        int row = e0 + ei * 8 + r;
        if (row <= NTAB) {
            float* dst = g_table + (size_t)row * CH + c0;
            *reinterpret_cast<float4*>(dst)     = make_float4(acc[r][0], acc[r][1], acc[r][2], acc[r][3]);
            *reinterpret_cast<float4*>(dst + 4) = make_float4(acc[r][4], acc[r][5], acc[r][6], acc[r][7]);
        }
    }
}

// ---------------------------------------------------------------------------
// Edge apply (frozen R9 form): warp owns 32 consecutive edges, depth-1
// prefetch; fp16 endpoint table (L1-resident) + fp16 h; red scatter.
// ---------------------------------------------------------------------------
__global__ __launch_bounds__(256, 8)
void edge_apply_kernel(const float* __restrict__ dist,
                       const int* __restrict__ senders,
                       const int* __restrict__ receivers)
{
    const int lane = threadIdx.x & 31;
    const int warp = (blockIdx.x * blockDim.x + threadIdx.x) >> 5;
    const int nwarps = (gridDim.x * blockDim.x) >> 5;
    const float SCALE = (float)NTAB / 5.0f;
    const unsigned FULL = 0xFFFFFFFFu;

    for (int c = warp; c < NCHUNK; c += nwarps) {
        const int e0 = c << 5;
        float dl = __ldg(dist + e0 + lane);
        int   sl = __ldg(senders + e0 + lane);
        int   rl = __ldg(receivers + e0 + lane);

        float d0 = __shfl_sync(FULL, dl, 0);
        int   s0 = __shfl_sync(FULL, sl, 0);
        float u = d0 * SCALE;
        int   i = (int)u;  i = i < 0 ? 0 : (i > NTAB - 1 ? NTAB - 1 : i);
        float fcur = u - (float)i;
        uint4 tw = __ldg(reinterpret_cast<const uint4*>(
            g_tab2 + (size_t)i * CH) + lane);
        uint2 hw = __ldg(reinterpret_cast<const uint2*>(g_h2 + (size_t)s0 * 64) + lane);

        #pragma unroll 1
        for (int k = 0; k < 32; k++) {
            const int kn = (k + 1 < 32) ? k + 1 : 31;
            float dn = __shfl_sync(FULL, dl, kn);
            int   sn = __shfl_sync(FULL, sl, kn);
            float un = dn * SCALE;
            int   in = (int)un;  in = in < 0 ? 0 : (in > NTAB - 1 ? NTAB - 1 : in);
            float fn = un - (float)in;
            uint4 twn = __ldg(reinterpret_cast<const uint4*>(
                g_tab2 + (size_t)in * CH) + lane);
            uint2 hwn = __ldg(reinterpret_cast<const uint2*>(g_h2 + (size_t)sn * 64) + lane);

            int rk = __shfl_sync(FULL, rl, k);
            float2 p0 = __half22float2(*reinterpret_cast<__half2*>(&tw.x));
            float2 p1 = __half22float2(*reinterpret_cast<__half2*>(&tw.y));
            float2 p2 = __half22float2(*reinterpret_cast<__half2*>(&tw.z));
            float2 p3 = __half22float2(*reinterpret_cast<__half2*>(&tw.w));
            float2 h01 = __half22float2(*reinterpret_cast<__half2*>(&hw.x));
            float2 h23 = __half22float2(*reinterpret_cast<__half2*>(&hw.y));
            float4 m;
            m.x = fmaf(fcur, p0.y - p0.x, p0.x) * h01.x;
            m.y = fmaf(fcur, p1.y - p1.x, p1.x) * h01.y;
            m.z = fmaf(fcur, p2.y - p2.x, p2.x) * h23.x;
            m.w = fmaf(fcur, p3.y - p3.x, p3.x) * h23.y;
            red_add_v4(g_agg + (size_t)rk * CH + lane * 4, m);

            tw = twn; hw = hwn; fcur = fn;
        }
    }
}

// ---------------------------------------------------------------------------
extern "C" void kernel_launch(void* const* d_in, const int* in_sizes, int n_in,
                              void* d_out, int out_size)
{
    const float* features = (const float*)d_in[0];
    const float* dist     = (const float*)d_in[1];
    const float* W_lin    = (const float*)d_in[2];
    const float* Wf1      = (const float*)d_in[3];
    const float* bf1      = (const float*)d_in[4];
    const float* Wf2      = (const float*)d_in[5];
    const float* bf2      = (const float*)d_in[6];
    const float* Wm1      = (const float*)d_in[7];
    const float* bm1      = (const float*)d_in[8];
    const float* Wm2      = (const float*)d_in[9];
    const float* bm2      = (const float*)d_in[10];
    const int*   senders   = (const int*)d_in[11];
    const int*   receivers = (const int*)d_in[12];
    float* out = (float*)d_out;

    const int smemA = 128 * TS * 4;
    const int smemT = (FE * CH + CH * CH + 2 * CH + 128 * 53 + 128 * 130) * 4;
    const int smemC = (64 * TS + 2 * CH) * 4;

    // One-time resources (created on the first, uncaptured correctness call —
    // before the harness's pre-capture memory baseline).
    static cudaStream_t s2 = nullptr, s3 = nullptr;
    static cudaEvent_t eFork = nullptr, eJoin2 = nullptr, eJoin3 = nullptr;
    static bool init_done = false;
    if (!init_done) {
        cudaStreamCreateWithFlags(&s2, cudaStreamNonBlocking);
        cudaStreamCreateWithFlags(&s3, cudaStreamNonBlocking);
        cudaEventCreateWithFlags(&eFork,  cudaEventDisableTiming);
        cudaEventCreateWithFlags(&eJoin2, cudaEventDisableTiming);
        cudaEventCreateWithFlags(&eJoin3, cudaEventDisableTiming);
        cudaFuncSetAttribute(node_linear_kernel, cudaFuncAttributeMaxDynamicSharedMemorySize, smemA);
        cudaFuncSetAttribute(table_kernel,       cudaFuncAttributeMaxDynamicSharedMemorySize, smemT);
        cudaFuncSetAttribute(out_mlp_kernel,     cudaFuncAttributeMaxDynamicSharedMemorySize, smemC);
        init_done = true;
    }

    cudaEventRecord(eFork, 0);
    cudaStreamWaitEvent(s2, eFork, 0);
    cudaStreamWaitEvent(s3, eFork, 0);

    // s2: build fp32 table, convert to fp16 endpoint table
    table_kernel<<<(NTAB + 1 + 127) / 128, 256, smemT, s2>>>(Wf1, bf1, Wf2, bf2);
    tab2_kernel<<<(NTAB * CH + 255) / 256, 256, 0, s2>>>();
    cudaEventRecord(eJoin2, s2);

    // s3: zero the aggregation buffer
    zero_agg_kernel<<<1024, 256, 0, s3>>>();
    cudaEventRecord(eJoin3, s3);

    // main: pack weights, node linear -> g_h2
    prep_pack_kernel<<<48, 256>>>(W_lin, Wm1, Wm2);
    node_linear_kernel<<<(NN + 127) / 128, 256, smemA>>>(features);

    cudaStreamWaitEvent(0, eJoin2, 0);
    cudaStreamWaitEvent(0, eJoin3, 0);
    edge_apply_kernel<<<2048, 256>>>(dist, senders, receivers);
    out_mlp_kernel<<<(NN + 63) / 64, 128, smemC>>>(bm1, bm2, out);
}